// round 7
// baseline (speedup 1.0000x reference)
#include <cuda_runtime.h>
#include <cuda_bf16.h>
#include <cstdint>

#define THREADS 512
#define RCOLS   224
#define MSTR    264     // Ms smem row stride (mod 32 == 8 -> conflict-free B frags)
#define XSTR    68      // Xs row stride (mod 32 == 4 -> conflict-free A frags)
#define GSTR    68
#define W1STR   72      // W1 row stride (mod 32 == 8)
#define TSTR    228     // t staging row stride (64 rows per half)

// Precomputed fused weight M[64][256] (tf32 bits; includes diag(s), proj, 0.25),
// bias row c[256] (fp32), and tf32-rounded W1.
__device__ __align__(16) float g_M[64 * 256];
__device__ __align__(16) float g_c[256];
__device__ __align__(16) float g_W1[64 * 64];

__device__ __forceinline__ uint32_t f2tf32(float f) {
    uint32_t u;
    asm("cvt.rna.tf32.f32 %0, %1;" : "=r"(u) : "f"(f));
    return u;
}

// ---------------------------------------------------------------------------
// Precompute, latency-optimized: c-loop split 4-way across threads, smem reduce.
// Blocks 0..64: M rows (64 = bias row). Blocks 65..68: W1 tf32 conversion.
// ---------------------------------------------------------------------------
__global__ __launch_bounds__(1024)
void precompute_kernel(const float* __restrict__ exp_w,
                       const float* __restrict__ exp_b,
                       const float* __restrict__ rad_w2,
                       const float* __restrict__ rad_b2,
                       const float* __restrict__ pw0,
                       const float* __restrict__ pw1,
                       const float* __restrict__ pw2,
                       const float* __restrict__ rad_w1) {
    int k = blockIdx.x;
    int tid = threadIdx.x;

    if (k >= 65) {                       // W1 conversion: 4 blocks x 1024
        int i = (k - 65) * 1024 + tid;
        if (i < 64 * 64) g_W1[i] = __uint_as_float(f2tf32(rad_w1[i]));
        return;
    }

    __shared__ float s_s[128];
    __shared__ float s_w[384];
    __shared__ float part[4][256];

    if (tid < 128) s_s[tid] = exp_w[tid] + exp_b[tid];
    if (tid >= 128 && tid < 512) {
        int i = tid - 128;
        s_w[i] = (k < 64) ? rad_w2[k * 384 + i] : rad_b2[i];
    }
    __syncthreads();

    const int cs  = tid >> 8;    // 0..3: c chunk
    const int col = tid & 255;   // 0..255
    float acc = 0.f;
    if (col < RCOLS) {
        const float* P;
        int d, woff, pstride;
        if (col < 128)      { P = pw0; d = col;       woff = 0;   pstride = 128; }
        else if (col < 192) { P = pw1; d = col - 128; woff = 128; pstride = 64;  }
        else                { P = pw2; d = col - 192; woff = 256; pstride = 32;  }
        const int c0 = cs * 32;
        #pragma unroll 8
        for (int c = c0; c < c0 + 32; c++)
            acc += s_w[woff + c] * s_s[c] * __ldg(&P[c * pstride + d]);
    }
    part[cs][col] = acc;
    __syncthreads();

    if (tid < 256) {
        float sum = (part[0][tid] + part[1][tid]) + (part[2][tid] + part[3][tid]);
        sum *= 0.25f;   // 1/sqrt(AVG_AGG)
        if (k < 64) g_M[k * 256 + tid] = __uint_as_float(f2tf32(sum));
        else        g_c[tid] = sum;
    }
}

// ---------------------------------------------------------------------------
__device__ __forceinline__ void red4(float* p, float a, float b, float c, float d) {
    asm volatile("red.global.add.v4.f32 [%0], {%1, %2, %3, %4};"
                 :: "l"(p), "f"(a), "f"(b), "f"(c), "f"(d) : "memory");
}

__device__ __forceinline__ void cp_async16(void* smem_ptr, const void* gmem) {
    uint32_t s = (uint32_t)__cvta_generic_to_shared(smem_ptr);
    asm volatile("cp.async.cg.shared.global [%0], [%1], 16;" :: "r"(s), "l"(gmem));
}
__device__ __forceinline__ void cp_async16_zfill(void* smem_ptr, const void* gmem, int srcsz) {
    uint32_t s = (uint32_t)__cvta_generic_to_shared(smem_ptr);
    asm volatile("cp.async.cg.shared.global [%0], [%1], 16, %2;"
                 :: "r"(s), "l"(gmem), "r"(srcsz));
}
__device__ __forceinline__ void cp_async4_zfill(void* smem_ptr, const void* gmem, int srcsz) {
    uint32_t s = (uint32_t)__cvta_generic_to_shared(smem_ptr);
    asm volatile("cp.async.ca.shared.global [%0], [%1], 4, %2;"
                 :: "r"(s), "l"(gmem), "r"(srcsz));
}

__device__ __forceinline__ void mma_tf32(float d[4], const uint32_t a[4],
                                         uint32_t b0, uint32_t b1) {
    asm volatile(
        "mma.sync.aligned.m16n8k8.row.col.f32.tf32.tf32.f32 "
        "{%0,%1,%2,%3}, {%4,%5,%6,%7}, {%8,%9}, {%0,%1,%2,%3};"
        : "+f"(d[0]), "+f"(d[1]), "+f"(d[2]), "+f"(d[3])
        : "r"(a[0]), "r"(a[1]), "r"(a[2]), "r"(a[3]), "r"(b0), "r"(b1));
}

// ---------------------------------------------------------------------------
// Persistent kernel: each CTA loops over 128-edge tiles (stride gridDim).
// M/W1 loaded once; next-tile X/sh/dst prefetched behind LN+stageB+scatter.
// ---------------------------------------------------------------------------
__global__ __launch_bounds__(THREADS, 1)
void edge_main_kernel(const float* __restrict__ edge_attr,
                      const float* __restrict__ edge_scalars,
                      const int*   __restrict__ edge_dst,
                      const float* __restrict__ rad_b1,
                      const float* __restrict__ rad_gamma,
                      const float* __restrict__ rad_beta,
                      const float* __restrict__ proj_b0,
                      float* __restrict__ out,
                      int E, int nTiles)
{
    extern __shared__ float smem[];
    float* Ms   = smem;                     // 16896
    float* W1s  = Ms + 64 * MSTR;           // 4608
    float* Xs   = W1s + 64 * W1STR;         // 8704
    float* Gs   = Xs + 128 * XSTR;          // 8704
    float* tS   = Gs + 128 * GSTR;          // 64*228 = 14592
    float* shS0 = tS + 64 * TSTR;           // 1280
    float* shS1 = shS0 + 128 * 10;          // 1280
    int*   dstS0 = (int*)(shS1 + 128 * 10); // 128
    int*   dstS1 = dstS0 + 128;             // 128
    float* b1s  = (float*)(dstS1 + 128);    // 64
    float* gms  = b1s + 64;                 // 64
    float* bts  = gms + 64;                 // 64
    float* cS   = bts + 64;                 // 256
    float* b0s  = cS + 256;                 // 128

    const int tid = threadIdx.x;
    const int l   = tid & 31;
    const int w   = tid >> 5;
    const int mg  = w & 3;       // stage-B m group
    const int ng  = w >> 2;      // stage-B n group

    // -------- one-time loads: M, W1, constants --------
    for (int i = tid; i < 64 * 64; i += THREADS) {
        int k = i >> 6, c4 = i & 63;
        cp_async16(&Ms[k * MSTR + c4 * 4], &g_M[k * 256 + c4 * 4]);
    }
    for (int i = tid; i < 64 * 16; i += THREADS) {
        int k = i >> 4, c4 = i & 15;
        cp_async16(&W1s[k * W1STR + c4 * 4], &g_W1[k * 64 + c4 * 4]);
    }
    if (tid < 64) { b1s[tid] = rad_b1[tid]; gms[tid] = rad_gamma[tid]; bts[tid] = rad_beta[tid]; }
    if (tid >= 64 && tid < 64 + 256) cS[tid - 64] = g_c[tid - 64];
    if (tid >= 320 && tid < 448) b0s[tid - 320] = proj_b0[tid - 320] * 0.25f;

    // -------- tile prefetch helper --------
    auto prefetch = [&](int e0, float* shB, int* dstB) {
        for (int i = tid; i < 128 * 16; i += THREADS) {
            int e = i >> 4, c4 = i & 15;
            int ge = e0 + e;
            int gc = (ge < E) ? ge : (E - 1);
            cp_async16_zfill(&Xs[e * XSTR + c4 * 4],
                             edge_scalars + (size_t)gc * 64 + c4 * 4,
                             (ge < E) ? 16 : 0);
        }
        for (int i = tid; i < 128 * 9; i += THREADS) {
            int e = i / 9, m = i - 9 * e;
            int ge = e0 + e;
            int gc = (ge < E) ? ge : (E - 1);
            cp_async4_zfill(&shB[e * 10 + m], edge_attr + (size_t)gc * 9 + m,
                            (ge < E) ? 4 : 0);
        }
        if (tid < 32) {
            int off = tid * 4;
            int ge = e0 + off;
            int gc = (ge + 3 < E) ? ge : ((E >= 4) ? E - 4 : 0);
            int rem = E - ge;
            int sz = (rem >= 4) ? 16 : ((rem > 0) ? rem * 4 : 0);
            cp_async16_zfill(&dstB[off], edge_dst + gc, sz);
        }
    };

    int t0 = blockIdx.x;
    if (t0 < nTiles) prefetch(t0 * 128, shS0, dstS0);
    asm volatile("cp.async.commit_group;" ::: "memory");

    int p = 0;
    for (int t = t0; t < nTiles; t += gridDim.x) {
        const int e0 = t * 128;
        float* shP  = p ? shS1 : shS0;
        int*   dstP = p ? dstS1 : dstS0;

        asm volatile("cp.async.wait_group 0;" ::: "memory");
        __syncthreads();

        // -------- stage A: h[128x64] = X @ W1 (mma tf32) --------
        {
            const int mt = w >> 1;
            const int nq = w & 1;
            const int m0 = mt * 16;
            float d[4][4] = {};
            const int ar0 = (m0 + (l >> 2)) * XSTR + (l & 3);
            const int ar1 = ar0 + 8 * XSTR;
            const uint32_t* W1u = (const uint32_t*)W1s;

            #pragma unroll
            for (int k0 = 0; k0 < 64; k0 += 8) {
                uint32_t a[4];
                a[0] = f2tf32(Xs[ar0 + k0]);
                a[1] = f2tf32(Xs[ar1 + k0]);
                a[2] = f2tf32(Xs[ar0 + k0 + 4]);
                a[3] = f2tf32(Xs[ar1 + k0 + 4]);
                #pragma unroll
                for (int nt = 0; nt < 4; nt++) {
                    int n0 = (nq * 4 + nt) * 8;
                    uint32_t b0 = W1u[(k0 + (l & 3)) * W1STR + n0 + (l >> 2)];
                    uint32_t b1 = W1u[(k0 + (l & 3) + 4) * W1STR + n0 + (l >> 2)];
                    mma_tf32(d[nt], a, b0, b1);
                }
            }
            // store raw h into Gs (private buffer, no hazard before the barrier)
            #pragma unroll
            for (int nt = 0; nt < 4; nt++) {
                int c  = (nq * 4 + nt) * 8 + (l & 3) * 2;
                int r0 = m0 + (l >> 2);
                *(float2*)&Gs[r0 * GSTR + c]       = make_float2(d[nt][0], d[nt][1]);
                *(float2*)&Gs[(r0 + 8) * GSTR + c] = make_float2(d[nt][2], d[nt][3]);
            }
        }
        __syncthreads();   // Xs reads done AND h stores visible (merged barrier)

        // -------- prefetch next tile's X/sh/dst (Xs now dead) --------
        {
            int tn = t + gridDim.x;
            if (tn < nTiles) prefetch(tn * 128, p ? shS0 : shS1, p ? dstS0 : dstS1);
            asm volatile("cp.async.commit_group;" ::: "memory");
        }

        // -------- LN + silu + tf32 convert (in place on Gs) --------
        {
            const int row = tid >> 2;
            const int qd  = tid & 3;
            float* hp = &Gs[row * GSTR + qd * 16];
            float v[16];
            float ps = 0.f, pq = 0.f;
            #pragma unroll
            for (int j = 0; j < 4; j++) {
                float4 x = ((const float4*)hp)[j];
                float b0 = b1s[qd * 16 + j * 4 + 0], b1 = b1s[qd * 16 + j * 4 + 1];
                float b2 = b1s[qd * 16 + j * 4 + 2], b3 = b1s[qd * 16 + j * 4 + 3];
                v[j * 4 + 0] = x.x + b0; v[j * 4 + 1] = x.y + b1;
                v[j * 4 + 2] = x.z + b2; v[j * 4 + 3] = x.w + b3;
                #pragma unroll
                for (int u = 0; u < 4; u++) { ps += v[j * 4 + u]; pq += v[j * 4 + u] * v[j * 4 + u]; }
            }
            ps += __shfl_xor_sync(0xffffffffu, ps, 1);
            pq += __shfl_xor_sync(0xffffffffu, pq, 1);
            ps += __shfl_xor_sync(0xffffffffu, ps, 2);
            pq += __shfl_xor_sync(0xffffffffu, pq, 2);
            float mu   = ps * (1.f / 64.f);
            float var  = pq * (1.f / 64.f) - mu * mu;
            float rstd = rsqrtf(var + 1e-5f);
            uint32_t o[16];
            #pragma unroll
            for (int u = 0; u < 16; u++) {
                int jj = qd * 16 + u;
                float g = (v[u] - mu) * rstd * gms[jj] + bts[jj];
                g = __fdividef(g, 1.f + __expf(-g));   // silu
                o[u] = f2tf32(g);
            }
            #pragma unroll
            for (int j = 0; j < 4; j++)
                ((uint4*)hp)[j] = make_uint4(o[j * 4], o[j * 4 + 1], o[j * 4 + 2], o[j * 4 + 3]);
        }
        __syncthreads();

        // -------- stage B: t[128x224] = G @ M + c (mma tf32) --------
        float d[2][7][4] = {};
        {
            const int m0 = mg * 32;
            const int n0 = ng * 56;
            const uint32_t* Gu = (const uint32_t*)Gs;
            const uint32_t* Mu = (const uint32_t*)Ms;
            const int ar00 = (m0 + (l >> 2)) * GSTR + (l & 3);

            #pragma unroll
            for (int k0 = 0; k0 < 64; k0 += 8) {
                uint32_t a[2][4];
                #pragma unroll
                for (int mt = 0; mt < 2; mt++) {
                    int base = ar00 + mt * 16 * GSTR + k0;
                    a[mt][0] = Gu[base];
                    a[mt][1] = Gu[base + 8 * GSTR];
                    a[mt][2] = Gu[base + 4];
                    a[mt][3] = Gu[base + 8 * GSTR + 4];
                }
                const int brow = (k0 + (l & 3)) * MSTR + n0 + (l >> 2);
                #pragma unroll
                for (int jt = 0; jt < 7; jt++) {
                    uint32_t b0 = Mu[brow + jt * 8];
                    uint32_t b1 = Mu[brow + 4 * MSTR + jt * 8];
                    mma_tf32(d[0][jt], a[0], b0, b1);
                    mma_tf32(d[1][jt], a[1], b0, b1);
                }
            }
        }

        // -------- stage C: two halves of 64 edges --------
        #pragma unroll
        for (int half = 0; half < 2; half++) {
            __syncthreads();   // prev tS reads done
            if ((mg >> 1) == half) {
                const int m0 = mg * 32 - half * 64;   // 0 or 32
                const int n0 = ng * 56;
                #pragma unroll
                for (int jt = 0; jt < 7; jt++) {
                    int c = n0 + jt * 8 + (l & 3) * 2;
                    float c0 = cS[c], c1 = cS[c + 1];
                    #pragma unroll
                    for (int mt = 0; mt < 2; mt++) {
                        int r0 = m0 + mt * 16 + (l >> 2);
                        *(float2*)&tS[r0 * TSTR + c] =
                            make_float2(d[mt][jt][0] + c0, d[mt][jt][1] + c1);
                        *(float2*)&tS[(r0 + 8) * TSTR + c] =
                            make_float2(d[mt][jt][2] + c0, d[mt][jt][3] + c1);
                    }
                }
            }
            __syncthreads();

            // ---- balanced lane-aligned scatter: 16 warps x 4 edges ----
            const float4 b0v = *(const float4*)&b0s[l * 4];
            #pragma unroll 1
            for (int i = 0; i < 4; i++) {
                const int er = w * 4 + i;             // row in tS
                const int e  = half * 64 + er;        // edge in tile
                if (e0 + e >= E) continue;
                const float* te = &tS[er * TSTR];
                const float* sh = &shP[e * 10];
                float* base = out + (size_t)dstP[e] * 480;

                // region 0: lane l owns y[4l..4l+3] = s0*t[4l..] + b0
                const float s0 = sh[0];
                {
                    float4 v = *(const float4*)&te[l * 4];
                    red4(base + l * 4,
                         fmaf(s0, v.x, b0v.x), fmaf(s0, v.y, b0v.y),
                         fmaf(s0, v.z, b0v.z), fmaf(s0, v.w, b0v.w));
                }
                if (l < 16) {
                    // region 1: lane l owns t1[4l..4l+3] -> y[128+12l .. +11]
                    float4 t4 = *(const float4*)&te[128 + l * 4];
                    float sa = sh[1], sb = sh[2], sc = sh[3];
                    float* b1 = base + 128 + 12 * l;
                    red4(b1,     t4.x*sa, t4.x*sb, t4.x*sc, t4.y*sa);
                    red4(b1 + 4, t4.y*sb, t4.y*sc, t4.z*sa, t4.z*sb);
                    red4(b1 + 8, t4.z*sc, t4.w*sa, t4.w*sb, t4.w*sc);
                } else {
                    // region 2: quad p owned by lanes 16+p (groups 0-2)
                    //           and 24+p (groups 3-4); y[320+20p .. +19]
                    int pq = (l - 16) & 7;
                    float4 t4 = *(const float4*)&te[192 + pq * 4];
                    float sa = sh[4], sb = sh[5], sc = sh[6], sd = sh[7], sf = sh[8];
                    float* b2 = base + 320 + 20 * pq;
                    if (l < 24) {
                        red4(b2,     t4.x*sa, t4.x*sb, t4.x*sc, t4.x*sd);
                        red4(b2 + 4, t4.x*sf, t4.y*sa, t4.y*sb, t4.y*sc);
                        red4(b2 + 8, t4.y*sd, t4.y*sf, t4.z*sa, t4.z*sb);
                    } else {
                        red4(b2 + 12, t4.z*sc, t4.z*sd, t4.z*sf, t4.w*sa);
                        red4(b2 + 16, t4.w*sb, t4.w*sc, t4.w*sd, t4.w*sf);
                    }
                }
            }
        }
        p ^= 1;
    }
}

// ---------------------------------------------------------------------------
extern "C" void kernel_launch(void* const* d_in, const int* in_sizes, int n_in,
                              void* d_out, int out_size) {
    const float* edge_attr    = (const float*)d_in[1];
    const float* edge_scalars = (const float*)d_in[2];
    const int*   edge_dst     = (const int*)d_in[4];
    const float* exp_w   = (const float*)d_in[6];
    const float* exp_b   = (const float*)d_in[7];
    const float* rad_w1  = (const float*)d_in[8];
    const float* rad_b1  = (const float*)d_in[9];
    const float* rad_gamma = (const float*)d_in[10];
    const float* rad_beta  = (const float*)d_in[11];
    const float* rad_w2  = (const float*)d_in[12];
    const float* rad_b2  = (const float*)d_in[13];
    const float* proj_w0 = (const float*)d_in[14];
    const float* proj_b0 = (const float*)d_in[15];
    const float* proj_w1 = (const float*)d_in[16];
    const float* proj_w2 = (const float*)d_in[17];
    float* out = (float*)d_out;
    const int E = in_sizes[4];

    cudaMemsetAsync(d_out, 0, (size_t)out_size * sizeof(float));

    precompute_kernel<<<69, 1024>>>(exp_w, exp_b, rad_w2, rad_b2,
                                    proj_w0, proj_w1, proj_w2, rad_w1);

    const size_t SMEM_FLOATS =
        64 * MSTR + 64 * W1STR + 128 * XSTR + 128 * GSTR + 64 * TSTR +
        2 * 128 * 10 + 2 * 128 + 64 * 3 + 256 + 128;
    const size_t SMEM_BYTES = SMEM_FLOATS * sizeof(float);
    cudaFuncSetAttribute(edge_main_kernel,
                         cudaFuncAttributeMaxDynamicSharedMemorySize, (int)SMEM_BYTES);

    int sms = 148;
    cudaDeviceGetAttribute(&sms, cudaDevAttrMultiProcessorCount, 0);
    const int nTiles = (E + 127) / 128;
    const int grid = (nTiles < sms) ? nTiles : sms;

    edge_main_kernel<<<grid, THREADS, SMEM_BYTES>>>(
        edge_attr, edge_scalars, edge_dst,
        rad_b1, rad_gamma, rad_beta,
        proj_b0, out, E, nTiles);
}

// round 8
// speedup vs baseline: 1.2756x; 1.2756x over previous
#include <cuda_runtime.h>
#include <cuda_bf16.h>
#include <cstdint>

#define THREADS 512
#define RCOLS   224
#define MSTR    264     // Ms smem row stride (mod 32 == 8 -> conflict-free B frags)
#define XSTR    68      // Xs row stride (mod 32 == 4 -> conflict-free A frags)
#define GSTR    68
#define W1STR   72      // W1 row stride (mod 32 == 8)
#define TSTR    228     // t staging row stride (64 rows per half)

// Precomputed fused weight M[64][256] (tf32 bits; includes diag(s), proj, 0.25),
// bias row c[256] (fp32), and tf32-rounded W1.
__device__ __align__(16) float g_M[64 * 256];
__device__ __align__(16) float g_c[256];
__device__ __align__(16) float g_W1[64 * 64];

__device__ __forceinline__ uint32_t f2tf32(float f) {
    uint32_t u;
    asm("cvt.rna.tf32.f32 %0, %1;" : "=r"(u) : "f"(f));
    return u;
}

// ---------------------------------------------------------------------------
// Precompute: c-loop split 4-way across threads, smem reduce.
// Blocks 0..64: M rows (64 = bias row). Blocks 65..68: W1 tf32 conversion.
// ---------------------------------------------------------------------------
__global__ __launch_bounds__(1024)
void precompute_kernel(const float* __restrict__ exp_w,
                       const float* __restrict__ exp_b,
                       const float* __restrict__ rad_w2,
                       const float* __restrict__ rad_b2,
                       const float* __restrict__ pw0,
                       const float* __restrict__ pw1,
                       const float* __restrict__ pw2,
                       const float* __restrict__ rad_w1) {
    int k = blockIdx.x;
    int tid = threadIdx.x;

    if (k >= 65) {                       // W1 conversion: 4 blocks x 1024
        int i = (k - 65) * 1024 + tid;
        if (i < 64 * 64) g_W1[i] = __uint_as_float(f2tf32(rad_w1[i]));
        return;
    }

    __shared__ float s_s[128];
    __shared__ float s_w[384];
    __shared__ float part[4][256];

    if (tid < 128) s_s[tid] = exp_w[tid] + exp_b[tid];
    if (tid >= 128 && tid < 512) {
        int i = tid - 128;
        s_w[i] = (k < 64) ? rad_w2[k * 384 + i] : rad_b2[i];
    }
    __syncthreads();

    const int cs  = tid >> 8;    // 0..3: c chunk
    const int col = tid & 255;   // 0..255
    float acc = 0.f;
    if (col < RCOLS) {
        const float* P;
        int d, woff, pstride;
        if (col < 128)      { P = pw0; d = col;       woff = 0;   pstride = 128; }
        else if (col < 192) { P = pw1; d = col - 128; woff = 128; pstride = 64;  }
        else                { P = pw2; d = col - 192; woff = 256; pstride = 32;  }
        const int c0 = cs * 32;
        #pragma unroll 8
        for (int c = c0; c < c0 + 32; c++)
            acc += s_w[woff + c] * s_s[c] * __ldg(&P[c * pstride + d]);
    }
    part[cs][col] = acc;
    __syncthreads();

    if (tid < 256) {
        float sum = (part[0][tid] + part[1][tid]) + (part[2][tid] + part[3][tid]);
        sum *= 0.25f;   // 1/sqrt(AVG_AGG)
        if (k < 64) g_M[k * 256 + tid] = __uint_as_float(f2tf32(sum));
        else        g_c[tid] = sum;
    }
}

// ---------------------------------------------------------------------------
__device__ __forceinline__ void red4(float* p, float a, float b, float c, float d) {
    asm volatile("red.global.add.v4.f32 [%0], {%1, %2, %3, %4};"
                 :: "l"(p), "f"(a), "f"(b), "f"(c), "f"(d) : "memory");
}

__device__ __forceinline__ void cp_async16(void* smem_ptr, const void* gmem) {
    uint32_t s = (uint32_t)__cvta_generic_to_shared(smem_ptr);
    asm volatile("cp.async.cg.shared.global [%0], [%1], 16;" :: "r"(s), "l"(gmem));
}
__device__ __forceinline__ void cp_async16_zfill(void* smem_ptr, const void* gmem, int srcsz) {
    uint32_t s = (uint32_t)__cvta_generic_to_shared(smem_ptr);
    asm volatile("cp.async.cg.shared.global [%0], [%1], 16, %2;"
                 :: "r"(s), "l"(gmem), "r"(srcsz));
}

__device__ __forceinline__ void mma_tf32(float d[4], const uint32_t a[4],
                                         uint32_t b0, uint32_t b1) {
    asm volatile(
        "mma.sync.aligned.m16n8k8.row.col.f32.tf32.tf32.f32 "
        "{%0,%1,%2,%3}, {%4,%5,%6,%7}, {%8,%9}, {%0,%1,%2,%3};"
        : "+f"(d[0]), "+f"(d[1]), "+f"(d[2]), "+f"(d[3])
        : "r"(a[0]), "r"(a[1]), "r"(a[2]), "r"(a[3]), "r"(b0), "r"(b1));
}

// ---------------------------------------------------------------------------
// Persistent kernel: each CTA loops over 128-edge tiles (stride gridDim).
// M/W1 loaded once; next-tile X/sh/dst prefetched behind LN+stageB+scatter.
// LN fused into stage-A registers (partner-warp partial-sum exchange).
// ---------------------------------------------------------------------------
__global__ __launch_bounds__(THREADS, 1)
void edge_main_kernel(const float* __restrict__ edge_attr,
                      const float* __restrict__ edge_scalars,
                      const int*   __restrict__ edge_dst,
                      const float* __restrict__ rad_b1,
                      const float* __restrict__ rad_gamma,
                      const float* __restrict__ rad_beta,
                      const float* __restrict__ proj_b0,
                      float* __restrict__ out,
                      int E, int nTiles)
{
    extern __shared__ float smem[];
    float* Ms   = smem;                     // 16896
    float* W1s  = Ms + 64 * MSTR;           // 4608
    float* Xs   = W1s + 64 * W1STR;         // 8704
    float* Gs   = Xs + 128 * XSTR;          // 8704
    float* tS   = Gs + 128 * GSTR;          // 64*228 = 14592
    float* shS0 = tS + 64 * TSTR;           // 1152
    float* shS1 = shS0 + 1152;              // 1152
    int*   dstS0 = (int*)(shS1 + 1152);     // 128
    int*   dstS1 = dstS0 + 128;             // 128
    float* pbuf = (float*)(dstS1 + 128);    // 512 (16 warps x 8 quads x float4)
    float* b1s  = pbuf + 512;               // 64
    float* gms  = b1s + 64;                 // 64
    float* bts  = gms + 64;                 // 64
    float* cS   = bts + 64;                 // 256
    float* b0s  = cS + 256;                 // 128

    const int tid = threadIdx.x;
    const int l   = tid & 31;
    const int w   = tid >> 5;
    const int mg  = w & 3;       // stage-B m group
    const int ng  = w >> 2;      // stage-B n group

    // -------- one-time loads: M, W1, constants --------
    for (int i = tid; i < 64 * 64; i += THREADS) {
        int k = i >> 6, c4 = i & 63;
        cp_async16(&Ms[k * MSTR + c4 * 4], &g_M[k * 256 + c4 * 4]);
    }
    for (int i = tid; i < 64 * 16; i += THREADS) {
        int k = i >> 4, c4 = i & 15;
        cp_async16(&W1s[k * W1STR + c4 * 4], &g_W1[k * 64 + c4 * 4]);
    }
    if (tid < 64) { b1s[tid] = rad_b1[tid]; gms[tid] = rad_gamma[tid]; bts[tid] = rad_beta[tid]; }
    if (tid >= 64 && tid < 64 + 256) cS[tid - 64] = g_c[tid - 64];
    if (tid >= 320 && tid < 448) b0s[tid - 320] = proj_b0[tid - 320] * 0.25f;

    // -------- tile prefetch helper --------
    auto prefetch = [&](int e0, float* shB, int* dstB) {
        for (int i = tid; i < 128 * 16; i += THREADS) {
            int e = i >> 4, c4 = i & 15;
            int ge = e0 + e;
            int gc = (ge < E) ? ge : (E - 1);
            cp_async16_zfill(&Xs[e * XSTR + c4 * 4],
                             edge_scalars + (size_t)gc * 64 + c4 * 4,
                             (ge < E) ? 16 : 0);
        }
        // contiguous sh blob: 1152 floats = 288 x 16B (e0*9*4 is 16B aligned)
        {
            const float* shg = edge_attr + (size_t)e0 * 9;
            const long totf = (long)E * 9 - (long)e0 * 9;
            for (int i = tid; i < 288; i += THREADS) {
                long rem = totf - (long)i * 4;
                int sz = (rem >= 4) ? 16 : ((rem > 0) ? (int)(rem * 4) : 0);
                cp_async16_zfill(&shB[i * 4], shg + i * 4, sz);
            }
        }
        if (tid < 32) {
            int off = tid * 4;
            int ge = e0 + off;
            int gc = (ge + 3 < E) ? ge : ((E >= 4) ? E - 4 : 0);
            int rem = E - ge;
            int sz = (rem >= 4) ? 16 : ((rem > 0) ? rem * 4 : 0);
            cp_async16_zfill(&dstB[off], edge_dst + gc, sz);
        }
    };

    int t0 = blockIdx.x;
    if (t0 < nTiles) prefetch(t0 * 128, shS0, dstS0);
    asm volatile("cp.async.commit_group;" ::: "memory");

    int p = 0;
    for (int t = t0; t < nTiles; t += gridDim.x) {
        const int e0 = t * 128;
        float* shP  = p ? shS1 : shS0;
        int*   dstP = p ? dstS1 : dstS0;

        asm volatile("cp.async.wait_group 0;" ::: "memory");
        __syncthreads();

        // -------- stage A: h[128x64] = X @ W1 (mma tf32), LN fused --------
        {
            const int mt = w >> 1;
            const int nq = w & 1;
            const int m0 = mt * 16;
            float d[4][4] = {};
            const int ar0 = (m0 + (l >> 2)) * XSTR + (l & 3);
            const int ar1 = ar0 + 8 * XSTR;
            const uint32_t* W1u = (const uint32_t*)W1s;

            #pragma unroll
            for (int k0 = 0; k0 < 64; k0 += 8) {
                uint32_t a[4];
                a[0] = f2tf32(Xs[ar0 + k0]);
                a[1] = f2tf32(Xs[ar1 + k0]);
                a[2] = f2tf32(Xs[ar0 + k0 + 4]);
                a[3] = f2tf32(Xs[ar1 + k0 + 4]);
                #pragma unroll
                for (int nt = 0; nt < 4; nt++) {
                    int n0 = (nq * 4 + nt) * 8;
                    uint32_t b0 = W1u[(k0 + (l & 3)) * W1STR + n0 + (l >> 2)];
                    uint32_t b1 = W1u[(k0 + (l & 3) + 4) * W1STR + n0 + (l >> 2)];
                    mma_tf32(d[nt], a, b0, b1);
                }
            }

            // add bias; per-row partial sums over this warp's 32 cols
            float ps0 = 0.f, pq0 = 0.f, ps1 = 0.f, pq1 = 0.f;
            #pragma unroll
            for (int nt = 0; nt < 4; nt++) {
                int c = nq * 32 + nt * 8 + (l & 3) * 2;
                float b0 = b1s[c], b1 = b1s[c + 1];
                d[nt][0] += b0; d[nt][1] += b1;
                d[nt][2] += b0; d[nt][3] += b1;
                ps0 += d[nt][0] + d[nt][1];
                pq0 += d[nt][0] * d[nt][0] + d[nt][1] * d[nt][1];
                ps1 += d[nt][2] + d[nt][3];
                pq1 += d[nt][2] * d[nt][2] + d[nt][3] * d[nt][3];
            }
            // reduce across the 4 lanes of each quad (same row)
            #pragma unroll
            for (int o = 1; o <= 2; o <<= 1) {
                ps0 += __shfl_xor_sync(0xffffffffu, ps0, o);
                pq0 += __shfl_xor_sync(0xffffffffu, pq0, o);
                ps1 += __shfl_xor_sync(0xffffffffu, ps1, o);
                pq1 += __shfl_xor_sync(0xffffffffu, pq1, o);
            }
            if ((l & 3) == 0)
                *(float4*)&pbuf[(w * 8 + (l >> 2)) * 4] = make_float4(ps0, pq0, ps1, pq1);
            __syncthreads();   // partials visible; ALL stage-A Xs reads done

            // prefetch next tile (Xs now free)
            {
                int tn = t + gridDim.x;
                if (tn < nTiles) prefetch(tn * 128, p ? shS0 : shS1, p ? dstS0 : dstS1);
                asm volatile("cp.async.commit_group;" ::: "memory");
            }

            // merge partner warp's partials -> full 64-col row stats
            float4 pp = *(const float4*)&pbuf[((w ^ 1) * 8 + (l >> 2)) * 4];
            ps0 += pp.x; pq0 += pp.y; ps1 += pp.z; pq1 += pp.w;
            float mu0   = ps0 * (1.f / 64.f);
            float rstd0 = rsqrtf(pq0 * (1.f / 64.f) - mu0 * mu0 + 1e-5f);
            float mu1   = ps1 * (1.f / 64.f);
            float rstd1 = rsqrtf(pq1 * (1.f / 64.f) - mu1 * mu1 + 1e-5f);

            // normalize + silu + tf32, store G
            const int r0 = m0 + (l >> 2);
            #pragma unroll
            for (int nt = 0; nt < 4; nt++) {
                int c = nq * 32 + nt * 8 + (l & 3) * 2;
                float g0 = gms[c], g1 = gms[c + 1];
                float q0 = bts[c], q1 = bts[c + 1];
                float v00 = (d[nt][0] - mu0) * rstd0 * g0 + q0;
                float v01 = (d[nt][1] - mu0) * rstd0 * g1 + q1;
                float v10 = (d[nt][2] - mu1) * rstd1 * g0 + q0;
                float v11 = (d[nt][3] - mu1) * rstd1 * g1 + q1;
                v00 = __fdividef(v00, 1.f + __expf(-v00));
                v01 = __fdividef(v01, 1.f + __expf(-v01));
                v10 = __fdividef(v10, 1.f + __expf(-v10));
                v11 = __fdividef(v11, 1.f + __expf(-v11));
                uint2 u0 = make_uint2(f2tf32(v00), f2tf32(v01));
                uint2 u1 = make_uint2(f2tf32(v10), f2tf32(v11));
                *(uint2*)&Gs[r0 * GSTR + c]       = u0;
                *(uint2*)&Gs[(r0 + 8) * GSTR + c] = u1;
            }
        }
        __syncthreads();   // G visible to all

        // -------- stage B: t[128x224] = G @ M + c (mma tf32) --------
        float d[2][7][4] = {};
        {
            const int m0 = mg * 32;
            const int n0 = ng * 56;
            const uint32_t* Gu = (const uint32_t*)Gs;
            const uint32_t* Mu = (const uint32_t*)Ms;
            const int ar00 = (m0 + (l >> 2)) * GSTR + (l & 3);

            #pragma unroll
            for (int k0 = 0; k0 < 64; k0 += 8) {
                uint32_t a[2][4];
                #pragma unroll
                for (int mt = 0; mt < 2; mt++) {
                    int base = ar00 + mt * 16 * GSTR + k0;
                    a[mt][0] = Gu[base];
                    a[mt][1] = Gu[base + 8 * GSTR];
                    a[mt][2] = Gu[base + 4];
                    a[mt][3] = Gu[base + 8 * GSTR + 4];
                }
                const int brow = (k0 + (l & 3)) * MSTR + n0 + (l >> 2);
                #pragma unroll
                for (int jt = 0; jt < 7; jt++) {
                    uint32_t b0 = Mu[brow + jt * 8];
                    uint32_t b1 = Mu[brow + 4 * MSTR + jt * 8];
                    mma_tf32(d[0][jt], a[0], b0, b1);
                    mma_tf32(d[1][jt], a[1], b0, b1);
                }
            }
        }

        // -------- stage C: two halves of 64 edges --------
        #pragma unroll
        for (int half = 0; half < 2; half++) {
            __syncthreads();   // prev tS reads done / stage-B Gs reads done
            if ((mg >> 1) == half) {
                const int m0 = mg * 32 - half * 64;   // 0 or 32
                const int n0 = ng * 56;
                #pragma unroll
                for (int jt = 0; jt < 7; jt++) {
                    int c = n0 + jt * 8 + (l & 3) * 2;
                    float c0 = cS[c], c1 = cS[c + 1];
                    #pragma unroll
                    for (int mt = 0; mt < 2; mt++) {
                        int r0 = m0 + mt * 16 + (l >> 2);
                        *(float2*)&tS[r0 * TSTR + c] =
                            make_float2(d[mt][jt][0] + c0, d[mt][jt][1] + c1);
                        *(float2*)&tS[(r0 + 8) * TSTR + c] =
                            make_float2(d[mt][jt][2] + c0, d[mt][jt][3] + c1);
                    }
                }
            }
            __syncthreads();

            // balanced coalesced scatter: 16 warps x 4 edges (R6 pattern)
            const float4 b0v = *(const float4*)&b0s[l * 4];
            #pragma unroll 1
            for (int i = 0; i < 4; i++) {
                const int er = w * 4 + i;             // row in tS
                const int e  = half * 64 + er;        // edge in tile
                if (e0 + e >= E) continue;
                const float* te = &tS[er * TSTR];
                const float* sh = &shP[e * 9];
                float* base = out + (size_t)dstP[e] * 480;
                const float s0 = sh[0];

                {
                    float4 v = *(const float4*)&te[l * 4];
                    red4(base + l * 4,
                         fmaf(s0, v.x, b0v.x), fmaf(s0, v.y, b0v.y),
                         fmaf(s0, v.z, b0v.z), fmaf(s0, v.w, b0v.w));
                }
                #pragma unroll
                for (int r = 0; r < 2; r++) {
                    int j = l + r * 32;
                    if (j < 48) {
                        int pidx = 4 * j;
                        int q = (pidx * 0x5556) >> 16;
                        int m = pidx - 3 * q;
                        float ta = te[128 + q];
                        float tb = te[128 + q + 1];
                        float v[4];
                        #pragma unroll
                        for (int ii = 0; ii < 4; ii++) {
                            int mi = m + ii;
                            int f  = (mi >= 3);
                            float sv = sh[1 + mi - 3 * f];
                            v[ii] = (f ? tb : ta) * sv;
                        }
                        red4(base + 128 + pidx, v[0], v[1], v[2], v[3]);
                    }
                }
                #pragma unroll
                for (int r = 0; r < 2; r++) {
                    int j = l + r * 32;
                    if (j < 40) {
                        int pidx = 4 * j;
                        int q = (pidx * 0x3334) >> 16;
                        int m = pidx - 5 * q;
                        int qb = (q + 1 > 31) ? 31 : q + 1;
                        float ta = te[192 + q];
                        float tb = te[192 + qb];
                        float v[4];
                        #pragma unroll
                        for (int ii = 0; ii < 4; ii++) {
                            int mi = m + ii;
                            int f  = (mi >= 5);
                            float sv = sh[4 + mi - 5 * f];
                            v[ii] = (f ? tb : ta) * sv;
                        }
                        red4(base + 320 + pidx, v[0], v[1], v[2], v[3]);
                    }
                }
            }
        }
        p ^= 1;
    }
}

// ---------------------------------------------------------------------------
extern "C" void kernel_launch(void* const* d_in, const int* in_sizes, int n_in,
                              void* d_out, int out_size) {
    const float* edge_attr    = (const float*)d_in[1];
    const float* edge_scalars = (const float*)d_in[2];
    const int*   edge_dst     = (const int*)d_in[4];
    const float* exp_w   = (const float*)d_in[6];
    const float* exp_b   = (const float*)d_in[7];
    const float* rad_w1  = (const float*)d_in[8];
    const float* rad_b1  = (const float*)d_in[9];
    const float* rad_gamma = (const float*)d_in[10];
    const float* rad_beta  = (const float*)d_in[11];
    const float* rad_w2  = (const float*)d_in[12];
    const float* rad_b2  = (const float*)d_in[13];
    const float* proj_w0 = (const float*)d_in[14];
    const float* proj_b0 = (const float*)d_in[15];
    const float* proj_w1 = (const float*)d_in[16];
    const float* proj_w2 = (const float*)d_in[17];
    float* out = (float*)d_out;
    const int E = in_sizes[4];

    cudaMemsetAsync(d_out, 0, (size_t)out_size * sizeof(float));

    precompute_kernel<<<69, 1024>>>(exp_w, exp_b, rad_w2, rad_b2,
                                    proj_w0, proj_w1, proj_w2, rad_w1);

    const size_t SMEM_FLOATS =
        64 * MSTR + 64 * W1STR + 128 * XSTR + 128 * GSTR + 64 * TSTR +
        2 * 1152 + 2 * 128 + 512 + 64 * 3 + 256 + 128;
    const size_t SMEM_BYTES = SMEM_FLOATS * sizeof(float);
    cudaFuncSetAttribute(edge_main_kernel,
                         cudaFuncAttributeMaxDynamicSharedMemorySize, (int)SMEM_BYTES);

    int sms = 148;
    cudaDeviceGetAttribute(&sms, cudaDevAttrMultiProcessorCount, 0);
    const int nTiles = (E + 127) / 128;
    const int grid = (nTiles < sms) ? nTiles : sms;

    edge_main_kernel<<<grid, THREADS, SMEM_BYTES>>>(
        edge_attr, edge_scalars, edge_dst,
        rad_b1, rad_gamma, rad_beta,
        proj_b0, out, E, nTiles);
}

// round 9
// speedup vs baseline: 1.3172x; 1.0327x over previous
#include <cuda_runtime.h>
#include <cuda_bf16.h>
#include <cstdint>

#define THREADS 512
#define RCOLS   224
#define MSTR    264     // Ms smem row stride (mod 32 == 8 -> conflict-free B frags)
#define XSTR    68      // Xs row stride (mod 32 == 4 -> conflict-free A frags)
#define GSTR    68
#define W1STR   72      // W1 row stride (mod 32 == 8)
#define TSTR    228     // t staging row stride (32 rows per half)

// group-local smem block sizes (floats)
#define GRP_FLOATS (4352 + 4352 + 7296 + 2*576 + 2*64 + 256)   // 17536
#define CONST_OFF  (16896 + 4608 + 2 * GRP_FLOATS)             // 56576

// Precomputed fused weight M[64][256] (tf32 bits; includes diag(s), proj, 0.25),
// bias row c[256] (fp32), and tf32-rounded W1.
__device__ __align__(16) float g_M[64 * 256];
__device__ __align__(16) float g_c[256];
__device__ __align__(16) float g_W1[64 * 64];

__device__ __forceinline__ uint32_t f2tf32(float f) {
    uint32_t u;
    asm("cvt.rna.tf32.f32 %0, %1;" : "=r"(u) : "f"(f));
    return u;
}

// ---------------------------------------------------------------------------
// Precompute: c-loop split 4-way across threads, smem reduce.
// Blocks 0..64: M rows (64 = bias row). Blocks 65..68: W1 tf32 conversion.
// ---------------------------------------------------------------------------
__global__ __launch_bounds__(1024)
void precompute_kernel(const float* __restrict__ exp_w,
                       const float* __restrict__ exp_b,
                       const float* __restrict__ rad_w2,
                       const float* __restrict__ rad_b2,
                       const float* __restrict__ pw0,
                       const float* __restrict__ pw1,
                       const float* __restrict__ pw2,
                       const float* __restrict__ rad_w1) {
    int k = blockIdx.x;
    int tid = threadIdx.x;

    if (k >= 65) {                       // W1 conversion: 4 blocks x 1024
        int i = (k - 65) * 1024 + tid;
        if (i < 64 * 64) g_W1[i] = __uint_as_float(f2tf32(rad_w1[i]));
        return;
    }

    __shared__ float s_s[128];
    __shared__ float s_w[384];
    __shared__ float part[4][256];

    if (tid < 128) s_s[tid] = exp_w[tid] + exp_b[tid];
    if (tid >= 128 && tid < 512) {
        int i = tid - 128;
        s_w[i] = (k < 64) ? rad_w2[k * 384 + i] : rad_b2[i];
    }
    __syncthreads();

    const int cs  = tid >> 8;    // 0..3: c chunk
    const int col = tid & 255;   // 0..255
    float acc = 0.f;
    if (col < RCOLS) {
        const float* P;
        int d, woff, pstride;
        if (col < 128)      { P = pw0; d = col;       woff = 0;   pstride = 128; }
        else if (col < 192) { P = pw1; d = col - 128; woff = 128; pstride = 64;  }
        else                { P = pw2; d = col - 192; woff = 256; pstride = 32;  }
        const int c0 = cs * 32;
        #pragma unroll 8
        for (int c = c0; c < c0 + 32; c++)
            acc += s_w[woff + c] * s_s[c] * __ldg(&P[c * pstride + d]);
    }
    part[cs][col] = acc;
    __syncthreads();

    if (tid < 256) {
        float sum = (part[0][tid] + part[1][tid]) + (part[2][tid] + part[3][tid]);
        sum *= 0.25f;   // 1/sqrt(AVG_AGG)
        if (k < 64) g_M[k * 256 + tid] = __uint_as_float(f2tf32(sum));
        else        g_c[tid] = sum;
    }
}

// ---------------------------------------------------------------------------
__device__ __forceinline__ void red4(float* p, float a, float b, float c, float d) {
    asm volatile("red.global.add.v4.f32 [%0], {%1, %2, %3, %4};"
                 :: "l"(p), "f"(a), "f"(b), "f"(c), "f"(d) : "memory");
}

__device__ __forceinline__ void cp_async16(void* smem_ptr, const void* gmem) {
    uint32_t s = (uint32_t)__cvta_generic_to_shared(smem_ptr);
    asm volatile("cp.async.cg.shared.global [%0], [%1], 16;" :: "r"(s), "l"(gmem));
}
__device__ __forceinline__ void cp_async16_zfill(void* smem_ptr, const void* gmem, int srcsz) {
    uint32_t s = (uint32_t)__cvta_generic_to_shared(smem_ptr);
    asm volatile("cp.async.cg.shared.global [%0], [%1], 16, %2;"
                 :: "r"(s), "l"(gmem), "r"(srcsz));
}

__device__ __forceinline__ void mma_tf32(float d[4], const uint32_t a[4],
                                         uint32_t b0, uint32_t b1) {
    asm volatile(
        "mma.sync.aligned.m16n8k8.row.col.f32.tf32.tf32.f32 "
        "{%0,%1,%2,%3}, {%4,%5,%6,%7}, {%8,%9}, {%0,%1,%2,%3};"
        : "+f"(d[0]), "+f"(d[1]), "+f"(d[2]), "+f"(d[3])
        : "r"(a[0]), "r"(a[1]), "r"(a[2]), "r"(a[3]), "r"(b0), "r"(b1));
}

// group barrier (named): 256 threads of group g
__device__ __forceinline__ void barg(int g) {
    asm volatile("bar.sync %0, %1;" :: "r"(g + 1), "r"(256) : "memory");
}

// ---------------------------------------------------------------------------
// Persistent kernel, two independent 256-thread warp-groups per CTA.
// Each group owns a stream of 64-edge tiles; groups overlap GEMM vs scatter.
// ---------------------------------------------------------------------------
__global__ __launch_bounds__(THREADS, 1)
void edge_main_kernel(const float* __restrict__ edge_attr,
                      const float* __restrict__ edge_scalars,
                      const int*   __restrict__ edge_dst,
                      const float* __restrict__ rad_b1,
                      const float* __restrict__ rad_gamma,
                      const float* __restrict__ rad_beta,
                      const float* __restrict__ proj_b0,
                      float* __restrict__ out,
                      int E, int nTiles)
{
    extern __shared__ float smem[];
    float* Ms   = smem;                     // 16896
    float* W1s  = Ms + 64 * MSTR;           // 4608
    // constants
    float* b1s  = smem + CONST_OFF;         // 64
    float* gms  = b1s + 64;                 // 64
    float* bts  = gms + 64;                 // 64
    float* cS   = bts + 64;                 // 256
    float* b0s  = cS + 256;                 // 128

    const int tid = threadIdx.x;
    const int g   = tid >> 8;        // warp-group 0/1
    const int gt  = tid & 255;       // thread-in-group
    const int l   = tid & 31;
    const int wg  = (tid >> 5) & 7;  // warp-in-group 0..7

    // group-local buffers
    float* GB   = smem + 16896 + 4608 + g * GRP_FLOATS;
    float* Xs   = GB;                       // 64*68 = 4352
    float* Gs   = Xs + 4352;                // 64*68 = 4352
    float* tS   = Gs + 4352;                // 32*228 = 7296
    float* sh0  = tS + 7296;                // 576
    float* sh1  = sh0 + 576;                // 576
    int*   dst0 = (int*)(sh1 + 576);        // 64
    int*   dst1 = dst0 + 64;                // 64
    float* pbuf = (float*)(dst1 + 64);      // 256

    // -------- one-time loads (all 512 threads): M, W1, constants --------
    for (int i = tid; i < 64 * 64; i += THREADS) {
        int k = i >> 6, c4 = i & 63;
        cp_async16(&Ms[k * MSTR + c4 * 4], &g_M[k * 256 + c4 * 4]);
    }
    for (int i = tid; i < 64 * 16; i += THREADS) {
        int k = i >> 4, c4 = i & 15;
        cp_async16(&W1s[k * W1STR + c4 * 4], &g_W1[k * 64 + c4 * 4]);
    }
    if (tid < 64) { b1s[tid] = rad_b1[tid]; gms[tid] = rad_gamma[tid]; bts[tid] = rad_beta[tid]; }
    if (tid >= 64 && tid < 64 + 256) cS[tid - 64] = g_c[tid - 64];
    if (tid >= 320 && tid < 448) b0s[tid - 320] = proj_b0[tid - 320] * 0.25f;

    // -------- per-group tile prefetch (64 edges) --------
    auto prefetch = [&](int e0, float* shB, int* dstB) {
        #pragma unroll
        for (int r = 0; r < 4; r++) {
            int i = gt + r * 256;            // 0..1023
            int e = i >> 4, c4 = i & 15;
            int ge = e0 + e;
            int gc = (ge < E) ? ge : (E - 1);
            cp_async16_zfill(&Xs[e * XSTR + c4 * 4],
                             edge_scalars + (size_t)gc * 64 + c4 * 4,
                             (ge < E) ? 16 : 0);
        }
        // contiguous sh blob: 576 floats = 144 x 16B (e0*9*4 is 16B aligned)
        if (gt < 144) {
            const float* shg = edge_attr + (size_t)e0 * 9;
            long rem = (long)E * 9 - (long)e0 * 9 - (long)gt * 4;
            int sz = (rem >= 4) ? 16 : ((rem > 0) ? (int)(rem * 4) : 0);
            cp_async16_zfill(&shB[gt * 4], shg + gt * 4, sz);
        }
        if (gt < 16) {
            int off = gt * 4;
            int ge = e0 + off;
            int gc = (ge + 3 < E) ? ge : ((E >= 4) ? E - 4 : 0);
            int rem = E - ge;
            int sz = (rem >= 4) ? 16 : ((rem > 0) ? rem * 4 : 0);
            cp_async16_zfill(&dstB[off], edge_dst + gc, sz);
        }
    };

    const int stride = gridDim.x * 2;
    int t0 = blockIdx.x * 2 + g;
    if (t0 < nTiles) prefetch(t0 * 64, sh0, dst0);
    asm volatile("cp.async.commit_group;" ::: "memory");
    __syncthreads();   // constants visible; groups diverge after this

    int p = 0;
    for (int t = t0; t < nTiles; t += stride) {
        const int e0 = t * 64;
        float* shP  = p ? sh1 : sh0;
        int*   dstP = p ? dst1 : dst0;

        asm volatile("cp.async.wait_group 0;" ::: "memory");
        barg(g);

        // -------- stage A: h[64x64] = X @ W1 (mma tf32), LN fused --------
        {
            const int mt = wg >> 1;          // 0..3
            const int nq = wg & 1;
            const int m0 = mt * 16;
            float d[4][4] = {};
            const int ar0 = (m0 + (l >> 2)) * XSTR + (l & 3);
            const int ar1 = ar0 + 8 * XSTR;
            const uint32_t* W1u = (const uint32_t*)W1s;

            #pragma unroll
            for (int k0 = 0; k0 < 64; k0 += 8) {
                uint32_t a[4];
                a[0] = f2tf32(Xs[ar0 + k0]);
                a[1] = f2tf32(Xs[ar1 + k0]);
                a[2] = f2tf32(Xs[ar0 + k0 + 4]);
                a[3] = f2tf32(Xs[ar1 + k0 + 4]);
                #pragma unroll
                for (int nt = 0; nt < 4; nt++) {
                    int n0 = (nq * 4 + nt) * 8;
                    uint32_t b0 = W1u[(k0 + (l & 3)) * W1STR + n0 + (l >> 2)];
                    uint32_t b1 = W1u[(k0 + (l & 3) + 4) * W1STR + n0 + (l >> 2)];
                    mma_tf32(d[nt], a, b0, b1);
                }
            }

            // bias + per-row partial sums over this warp's 32 cols
            float ps0 = 0.f, pq0 = 0.f, ps1 = 0.f, pq1 = 0.f;
            #pragma unroll
            for (int nt = 0; nt < 4; nt++) {
                int c = nq * 32 + nt * 8 + (l & 3) * 2;
                float b0 = b1s[c], b1 = b1s[c + 1];
                d[nt][0] += b0; d[nt][1] += b1;
                d[nt][2] += b0; d[nt][3] += b1;
                ps0 += d[nt][0] + d[nt][1];
                pq0 += d[nt][0] * d[nt][0] + d[nt][1] * d[nt][1];
                ps1 += d[nt][2] + d[nt][3];
                pq1 += d[nt][2] * d[nt][2] + d[nt][3] * d[nt][3];
            }
            #pragma unroll
            for (int o = 1; o <= 2; o <<= 1) {
                ps0 += __shfl_xor_sync(0xffffffffu, ps0, o);
                pq0 += __shfl_xor_sync(0xffffffffu, pq0, o);
                ps1 += __shfl_xor_sync(0xffffffffu, ps1, o);
                pq1 += __shfl_xor_sync(0xffffffffu, pq1, o);
            }
            if ((l & 3) == 0)
                *(float4*)&pbuf[(wg * 8 + (l >> 2)) * 4] = make_float4(ps0, pq0, ps1, pq1);
            barg(g);   // partials visible; ALL stage-A Xs reads done

            // prefetch next tile (Xs now free)
            {
                int tn = t + stride;
                if (tn < nTiles) prefetch(tn * 64, p ? sh0 : sh1, p ? dst0 : dst1);
                asm volatile("cp.async.commit_group;" ::: "memory");
            }

            // merge partner warp's partials -> full 64-col row stats
            float4 pp = *(const float4*)&pbuf[((wg ^ 1) * 8 + (l >> 2)) * 4];
            ps0 += pp.x; pq0 += pp.y; ps1 += pp.z; pq1 += pp.w;
            float mu0   = ps0 * (1.f / 64.f);
            float rstd0 = rsqrtf(pq0 * (1.f / 64.f) - mu0 * mu0 + 1e-5f);
            float mu1   = ps1 * (1.f / 64.f);
            float rstd1 = rsqrtf(pq1 * (1.f / 64.f) - mu1 * mu1 + 1e-5f);

            // normalize + silu + tf32, store G
            const int r0 = m0 + (l >> 2);
            #pragma unroll
            for (int nt = 0; nt < 4; nt++) {
                int c = nq * 32 + nt * 8 + (l & 3) * 2;
                float g0 = gms[c], g1 = gms[c + 1];
                float q0 = bts[c], q1 = bts[c + 1];
                float v00 = (d[nt][0] - mu0) * rstd0 * g0 + q0;
                float v01 = (d[nt][1] - mu0) * rstd0 * g1 + q1;
                float v10 = (d[nt][2] - mu1) * rstd1 * g0 + q0;
                float v11 = (d[nt][3] - mu1) * rstd1 * g1 + q1;
                v00 = __fdividef(v00, 1.f + __expf(-v00));
                v01 = __fdividef(v01, 1.f + __expf(-v01));
                v10 = __fdividef(v10, 1.f + __expf(-v10));
                v11 = __fdividef(v11, 1.f + __expf(-v11));
                *(uint2*)&Gs[r0 * GSTR + c]       = make_uint2(f2tf32(v00), f2tf32(v01));
                *(uint2*)&Gs[(r0 + 8) * GSTR + c] = make_uint2(f2tf32(v10), f2tf32(v11));
            }
        }
        barg(g);   // G visible to group

        // -------- stage B: t[64x224] = G @ M + c (mma tf32) --------
        float d[2][7][4] = {};
        const int mg = wg & 1;
        const int ng = wg >> 1;          // 0..3
        {
            const int m0 = mg * 32;
            const int n0 = ng * 56;
            const uint32_t* Gu = (const uint32_t*)Gs;
            const uint32_t* Mu = (const uint32_t*)Ms;
            const int ar00 = (m0 + (l >> 2)) * GSTR + (l & 3);

            #pragma unroll
            for (int k0 = 0; k0 < 64; k0 += 8) {
                uint32_t a[2][4];
                #pragma unroll
                for (int mt = 0; mt < 2; mt++) {
                    int base = ar00 + mt * 16 * GSTR + k0;
                    a[mt][0] = Gu[base];
                    a[mt][1] = Gu[base + 8 * GSTR];
                    a[mt][2] = Gu[base + 4];
                    a[mt][3] = Gu[base + 8 * GSTR + 4];
                }
                const int brow = (k0 + (l & 3)) * MSTR + n0 + (l >> 2);
                #pragma unroll
                for (int jt = 0; jt < 7; jt++) {
                    uint32_t b0 = Mu[brow + jt * 8];
                    uint32_t b1 = Mu[brow + 4 * MSTR + jt * 8];
                    mma_tf32(d[0][jt], a[0], b0, b1);
                    mma_tf32(d[1][jt], a[1], b0, b1);
                }
            }
        }

        // -------- stage C: two halves of 32 edges --------
        #pragma unroll
        for (int half = 0; half < 2; half++) {
            barg(g);   // prev tS reads done / stage-B Gs reads done
            if (mg == half) {
                const int n0 = ng * 56;
                #pragma unroll
                for (int jt = 0; jt < 7; jt++) {
                    int c = n0 + jt * 8 + (l & 3) * 2;
                    float c0 = cS[c], c1 = cS[c + 1];
                    #pragma unroll
                    for (int mt = 0; mt < 2; mt++) {
                        int r0 = mt * 16 + (l >> 2);
                        *(float2*)&tS[r0 * TSTR + c] =
                            make_float2(d[mt][jt][0] + c0, d[mt][jt][1] + c1);
                        *(float2*)&tS[(r0 + 8) * TSTR + c] =
                            make_float2(d[mt][jt][2] + c0, d[mt][jt][3] + c1);
                    }
                }
            }
            barg(g);

            // balanced coalesced scatter: 8 warps x 4 edges
            const float4 b0v = *(const float4*)&b0s[l * 4];
            #pragma unroll 1
            for (int i = 0; i < 4; i++) {
                const int er = wg * 4 + i;            // row in tS (0..31)
                const int e  = half * 32 + er;        // edge in tile
                if (e0 + e >= E) continue;
                const float* te = &tS[er * TSTR];
                const float* sh = &shP[e * 9];
                float* base = out + (size_t)dstP[e] * 480;
                const float s0 = sh[0];

                {
                    float4 v = *(const float4*)&te[l * 4];
                    red4(base + l * 4,
                         fmaf(s0, v.x, b0v.x), fmaf(s0, v.y, b0v.y),
                         fmaf(s0, v.z, b0v.z), fmaf(s0, v.w, b0v.w));
                }
                #pragma unroll
                for (int r = 0; r < 2; r++) {
                    int j = l + r * 32;
                    if (j < 48) {
                        int pidx = 4 * j;
                        int q = (pidx * 0x5556) >> 16;
                        int m = pidx - 3 * q;
                        float ta = te[128 + q];
                        float tb = te[128 + q + 1];
                        float v[4];
                        #pragma unroll
                        for (int ii = 0; ii < 4; ii++) {
                            int mi = m + ii;
                            int f  = (mi >= 3);
                            float sv = sh[1 + mi - 3 * f];
                            v[ii] = (f ? tb : ta) * sv;
                        }
                        red4(base + 128 + pidx, v[0], v[1], v[2], v[3]);
                    }
                }
                #pragma unroll
                for (int r = 0; r < 2; r++) {
                    int j = l + r * 32;
                    if (j < 40) {
                        int pidx = 4 * j;
                        int q = (pidx * 0x3334) >> 16;
                        int m = pidx - 5 * q;
                        int qb = (q + 1 > 31) ? 31 : q + 1;
                        float ta = te[192 + q];
                        float tb = te[192 + qb];
                        float v[4];
                        #pragma unroll
                        for (int ii = 0; ii < 4; ii++) {
                            int mi = m + ii;
                            int f  = (mi >= 5);
                            float sv = sh[4 + mi - 5 * f];
                            v[ii] = (f ? tb : ta) * sv;
                        }
                        red4(base + 320 + pidx, v[0], v[1], v[2], v[3]);
                    }
                }
            }
        }
        p ^= 1;
    }
}

// ---------------------------------------------------------------------------
extern "C" void kernel_launch(void* const* d_in, const int* in_sizes, int n_in,
                              void* d_out, int out_size) {
    const float* edge_attr    = (const float*)d_in[1];
    const float* edge_scalars = (const float*)d_in[2];
    const int*   edge_dst     = (const int*)d_in[4];
    const float* exp_w   = (const float*)d_in[6];
    const float* exp_b   = (const float*)d_in[7];
    const float* rad_w1  = (const float*)d_in[8];
    const float* rad_b1  = (const float*)d_in[9];
    const float* rad_gamma = (const float*)d_in[10];
    const float* rad_beta  = (const float*)d_in[11];
    const float* rad_w2  = (const float*)d_in[12];
    const float* rad_b2  = (const float*)d_in[13];
    const float* proj_w0 = (const float*)d_in[14];
    const float* proj_b0 = (const float*)d_in[15];
    const float* proj_w1 = (const float*)d_in[16];
    const float* proj_w2 = (const float*)d_in[17];
    float* out = (float*)d_out;
    const int E = in_sizes[4];

    cudaMemsetAsync(d_out, 0, (size_t)out_size * sizeof(float));

    precompute_kernel<<<69, 1024>>>(exp_w, exp_b, rad_w2, rad_b2,
                                    proj_w0, proj_w1, proj_w2, rad_w1);

    const size_t SMEM_FLOATS = CONST_OFF + 64 * 3 + 256 + 128;   // 57152
    const size_t SMEM_BYTES = SMEM_FLOATS * sizeof(float);        // 228608
    cudaFuncSetAttribute(edge_main_kernel,
                         cudaFuncAttributeMaxDynamicSharedMemorySize, (int)SMEM_BYTES);

    int sms = 148;
    cudaDeviceGetAttribute(&sms, cudaDevAttrMultiProcessorCount, 0);
    const int nTiles = (E + 63) / 64;
    int grid = (nTiles + 1) / 2;
    if (grid > sms) grid = sms;

    edge_main_kernel<<<grid, THREADS, SMEM_BYTES>>>(
        edge_attr, edge_scalars, edge_dst,
        rad_b1, rad_gamma, rad_beta,
        proj_b0, out, E, nTiles);
}

// round 10
// speedup vs baseline: 1.3280x; 1.0082x over previous
#include <cuda_runtime.h>
#include <cuda_bf16.h>
#include <cstdint>

#define THREADS 512
#define RCOLS   224
#define MSTR2   228     // Ms row stride in float2 (mod 16 == 4 -> conflict-free LDS.64)
#define XSTR    68      // Xs row stride (mod 32 == 4 -> conflict-free A frags)
#define GSTR    68
#define W1STR2  68      // W1 row stride in float2 (mod 16 == 4)
#define TSTR    228     // t staging row stride (32 rows per half)

// group-local smem block sizes (floats)
#define GRP_FLOATS (4352 + 4352 + 7296 + 2*576 + 2*64 + 256)   // 17536
#define MS_FLOATS  (32 * MSTR2 * 2)                             // 14592
#define W1_FLOATS  (32 * W1STR2 * 2)                            // 4352
#define CONST_OFF  (MS_FLOATS + W1_FLOATS + 2 * GRP_FLOATS)     // 54016

// Precomputed fused weight M, row-pair packed:
//   g_M[(prow*224 + col)*2 + slot],  prow=(k>>3)*4+(k&3), slot=(k>>2)&1
// bias row c[256] (fp32), W1 packed the same way (64 cols).
__device__ __align__(16) float g_M[32 * 224 * 2];
__device__ __align__(16) float g_c[256];
__device__ __align__(16) float g_W1[32 * 64 * 2];

__device__ __forceinline__ uint32_t f2tf32(float f) {
    uint32_t u;
    asm("cvt.rna.tf32.f32 %0, %1;" : "=r"(u) : "f"(f));
    return u;
}

// ---------------------------------------------------------------------------
// Precompute: c-loop split 4-way across threads, smem reduce.
// Blocks 0..64: M rows (64 = bias row). Blocks 65..68: W1 tf32 conversion.
// Both weights written in row-pair-packed float2 layout.
// ---------------------------------------------------------------------------
__global__ __launch_bounds__(1024)
void precompute_kernel(const float* __restrict__ exp_w,
                       const float* __restrict__ exp_b,
                       const float* __restrict__ rad_w2,
                       const float* __restrict__ rad_b2,
                       const float* __restrict__ pw0,
                       const float* __restrict__ pw1,
                       const float* __restrict__ pw2,
                       const float* __restrict__ rad_w1) {
    int k = blockIdx.x;
    int tid = threadIdx.x;

    if (k >= 65) {                       // W1 conversion: 4 blocks x 1024
        int i = (k - 65) * 1024 + tid;
        if (i < 64 * 64) {
            int kk = i >> 6, col = i & 63;
            int prow = (kk >> 3) * 4 + (kk & 3);
            int slot = (kk >> 2) & 1;
            g_W1[prow * 128 + col * 2 + slot] = __uint_as_float(f2tf32(rad_w1[i]));
        }
        return;
    }

    __shared__ float s_s[128];
    __shared__ float s_w[384];
    __shared__ float part[4][256];

    if (tid < 128) s_s[tid] = exp_w[tid] + exp_b[tid];
    if (tid >= 128 && tid < 512) {
        int i = tid - 128;
        s_w[i] = (k < 64) ? rad_w2[k * 384 + i] : rad_b2[i];
    }
    __syncthreads();

    const int cs  = tid >> 8;    // 0..3: c chunk
    const int col = tid & 255;   // 0..255
    float acc = 0.f;
    if (col < RCOLS) {
        const float* P;
        int d, woff, pstride;
        if (col < 128)      { P = pw0; d = col;       woff = 0;   pstride = 128; }
        else if (col < 192) { P = pw1; d = col - 128; woff = 128; pstride = 64;  }
        else                { P = pw2; d = col - 192; woff = 256; pstride = 32;  }
        const int c0 = cs * 32;
        #pragma unroll 8
        for (int c = c0; c < c0 + 32; c++)
            acc += s_w[woff + c] * s_s[c] * __ldg(&P[c * pstride + d]);
    }
    part[cs][col] = acc;
    __syncthreads();

    if (tid < 256) {
        float sum = (part[0][tid] + part[1][tid]) + (part[2][tid] + part[3][tid]);
        sum *= 0.25f;   // 1/sqrt(AVG_AGG)
        if (k < 64) {
            if (tid < RCOLS) {
                int prow = (k >> 3) * 4 + (k & 3);
                int slot = (k >> 2) & 1;
                g_M[(prow * 224 + tid) * 2 + slot] = __uint_as_float(f2tf32(sum));
            }
        } else {
            g_c[tid] = sum;
        }
    }
}

// ---------------------------------------------------------------------------
__device__ __forceinline__ void red4(float* p, float a, float b, float c, float d) {
    asm volatile("red.global.add.v4.f32 [%0], {%1, %2, %3, %4};"
                 :: "l"(p), "f"(a), "f"(b), "f"(c), "f"(d) : "memory");
}

__device__ __forceinline__ void cp_async16(void* smem_ptr, const void* gmem) {
    uint32_t s = (uint32_t)__cvta_generic_to_shared(smem_ptr);
    asm volatile("cp.async.cg.shared.global [%0], [%1], 16;" :: "r"(s), "l"(gmem));
}
__device__ __forceinline__ void cp_async16_zfill(void* smem_ptr, const void* gmem, int srcsz) {
    uint32_t s = (uint32_t)__cvta_generic_to_shared(smem_ptr);
    asm volatile("cp.async.cg.shared.global [%0], [%1], 16, %2;"
                 :: "r"(s), "l"(gmem), "r"(srcsz));
}

__device__ __forceinline__ void mma_tf32(float d[4], const uint32_t a[4],
                                         uint32_t b0, uint32_t b1) {
    asm volatile(
        "mma.sync.aligned.m16n8k8.row.col.f32.tf32.tf32.f32 "
        "{%0,%1,%2,%3}, {%4,%5,%6,%7}, {%8,%9}, {%0,%1,%2,%3};"
        : "+f"(d[0]), "+f"(d[1]), "+f"(d[2]), "+f"(d[3])
        : "r"(a[0]), "r"(a[1]), "r"(a[2]), "r"(a[3]), "r"(b0), "r"(b1));
}

// group barrier (named): 256 threads of group g
__device__ __forceinline__ void barg(int g) {
    asm volatile("bar.sync %0, %1;" :: "r"(g + 1), "r"(256) : "memory");
}

// ---------------------------------------------------------------------------
// Persistent kernel, two independent 256-thread warp-groups per CTA.
// Each group owns a stream of 64-edge tiles; groups overlap GEMM vs scatter.
// B-operands (W1, M) in row-pair float2 layout -> LDS.64 fragment loads.
// ---------------------------------------------------------------------------
__global__ __launch_bounds__(THREADS, 1)
void edge_main_kernel(const float* __restrict__ edge_attr,
                      const float* __restrict__ edge_scalars,
                      const int*   __restrict__ edge_dst,
                      const float* __restrict__ rad_b1,
                      const float* __restrict__ rad_gamma,
                      const float* __restrict__ rad_beta,
                      const float* __restrict__ proj_b0,
                      float* __restrict__ out,
                      int E, int nTiles)
{
    extern __shared__ float smem[];
    float* Ms   = smem;                     // 14592 (32 x 228 float2)
    float* W1s  = Ms + MS_FLOATS;           // 4352  (32 x 68 float2)
    // constants
    float* b1s  = smem + CONST_OFF;         // 64
    float* gms  = b1s + 64;                 // 64
    float* bts  = gms + 64;                 // 64
    float* cS   = bts + 64;                 // 256
    float* b0s  = cS + 256;                 // 128

    const int tid = threadIdx.x;
    const int g   = tid >> 8;        // warp-group 0/1
    const int gt  = tid & 255;       // thread-in-group
    const int l   = tid & 31;
    const int wg  = (tid >> 5) & 7;  // warp-in-group 0..7

    // group-local buffers
    float* GB   = smem + MS_FLOATS + W1_FLOATS + g * GRP_FLOATS;
    float* Xs   = GB;                       // 64*68 = 4352
    float* Gs   = Xs + 4352;                // 64*68 = 4352
    float* tS   = Gs + 4352;                // 32*228 = 7296
    float* sh0  = tS + 7296;                // 576
    float* sh1  = sh0 + 576;                // 576
    int*   dst0 = (int*)(sh1 + 576);        // 64
    int*   dst1 = dst0 + 64;                // 64
    float* pbuf = (float*)(dst1 + 64);      // 256

    // -------- one-time loads (all 512 threads): M, W1, constants --------
    for (int i = tid; i < 32 * 112; i += THREADS) {
        int row = i / 112, c4 = i - row * 112;
        cp_async16(&Ms[row * (MSTR2 * 2) + c4 * 4], &g_M[row * 448 + c4 * 4]);
    }
    for (int i = tid; i < 32 * 32; i += THREADS) {
        int row = i >> 5, c4 = i & 31;
        cp_async16(&W1s[row * (W1STR2 * 2) + c4 * 4], &g_W1[row * 128 + c4 * 4]);
    }
    if (tid < 64) { b1s[tid] = rad_b1[tid]; gms[tid] = rad_gamma[tid]; bts[tid] = rad_beta[tid]; }
    if (tid >= 64 && tid < 64 + 256) cS[tid - 64] = g_c[tid - 64];
    if (tid >= 320 && tid < 448) b0s[tid - 320] = proj_b0[tid - 320] * 0.25f;

    // -------- per-group tile prefetch (64 edges) --------
    auto prefetch = [&](int e0, float* shB, int* dstB) {
        if (e0 + 64 <= E) {   // full tile: no bounds math
            const float* xg = edge_scalars + (size_t)e0 * 64;
            #pragma unroll
            for (int r = 0; r < 4; r++) {
                int i = gt + r * 256;            // 0..1023
                int e = i >> 4, c4 = i & 15;
                cp_async16(&Xs[e * XSTR + c4 * 4], xg + e * 64 + c4 * 4);
            }
            if (gt < 144)
                cp_async16(&shB[gt * 4], edge_attr + (size_t)e0 * 9 + gt * 4);
            if (gt < 16)
                cp_async16(&dstB[gt * 4], edge_dst + e0 + gt * 4);
        } else {
            #pragma unroll
            for (int r = 0; r < 4; r++) {
                int i = gt + r * 256;
                int e = i >> 4, c4 = i & 15;
                int ge = e0 + e;
                int gc = (ge < E) ? ge : (E - 1);
                cp_async16_zfill(&Xs[e * XSTR + c4 * 4],
                                 edge_scalars + (size_t)gc * 64 + c4 * 4,
                                 (ge < E) ? 16 : 0);
            }
            if (gt < 144) {
                long rem = (long)E * 9 - (long)e0 * 9 - (long)gt * 4;
                int sz = (rem >= 4) ? 16 : ((rem > 0) ? (int)(rem * 4) : 0);
                cp_async16_zfill(&shB[gt * 4], edge_attr + (size_t)e0 * 9 + gt * 4, sz);
            }
            if (gt < 16) {
                int off = gt * 4;
                int ge = e0 + off;
                int gc = (ge + 3 < E) ? ge : ((E >= 4) ? E - 4 : 0);
                int rem = E - ge;
                int sz = (rem >= 4) ? 16 : ((rem > 0) ? rem * 4 : 0);
                cp_async16_zfill(&dstB[off], edge_dst + gc, sz);
            }
        }
    };

    const int stride = gridDim.x * 2;
    int t0 = blockIdx.x * 2 + g;
    if (t0 < nTiles) prefetch(t0 * 64, sh0, dst0);
    asm volatile("cp.async.commit_group;" ::: "memory");
    __syncthreads();   // constants visible; groups diverge after this

    int p = 0;
    for (int t = t0; t < nTiles; t += stride) {
        const int e0 = t * 64;
        float* shP  = p ? sh1 : sh0;
        int*   dstP = p ? dst1 : dst0;

        asm volatile("cp.async.wait_group 0;" ::: "memory");
        barg(g);

        // -------- stage A: h[64x64] = X @ W1 (mma tf32), LN fused --------
        {
            const int mt = wg >> 1;          // 0..3
            const int nq = wg & 1;
            const int m0 = mt * 16;
            float d[4][4] = {};
            const int ar0 = (m0 + (l >> 2)) * XSTR + (l & 3);
            const int ar1 = ar0 + 8 * XSTR;
            const float2* W2 = (const float2*)W1s;
            const int wcol = nq * 32 + (l >> 2);   // float2 col base

            #pragma unroll
            for (int k0 = 0; k0 < 64; k0 += 8) {
                uint32_t a[4];
                a[0] = f2tf32(Xs[ar0 + k0]);
                a[1] = f2tf32(Xs[ar1 + k0]);
                a[2] = f2tf32(Xs[ar0 + k0 + 4]);
                a[3] = f2tf32(Xs[ar1 + k0 + 4]);
                const int wrow = ((k0 >> 3) * 4 + (l & 3)) * W1STR2 + wcol;
                #pragma unroll
                for (int nt = 0; nt < 4; nt++) {
                    float2 bb = W2[wrow + nt * 8];
                    mma_tf32(d[nt], a, __float_as_uint(bb.x), __float_as_uint(bb.y));
                }
            }

            // bias + per-row partial sums over this warp's 32 cols
            float ps0 = 0.f, pq0 = 0.f, ps1 = 0.f, pq1 = 0.f;
            #pragma unroll
            for (int nt = 0; nt < 4; nt++) {
                int c = nq * 32 + nt * 8 + (l & 3) * 2;
                float b0 = b1s[c], b1 = b1s[c + 1];
                d[nt][0] += b0; d[nt][1] += b1;
                d[nt][2] += b0; d[nt][3] += b1;
                ps0 += d[nt][0] + d[nt][1];
                pq0 += d[nt][0] * d[nt][0] + d[nt][1] * d[nt][1];
                ps1 += d[nt][2] + d[nt][3];
                pq1 += d[nt][2] * d[nt][2] + d[nt][3] * d[nt][3];
            }
            #pragma unroll
            for (int o = 1; o <= 2; o <<= 1) {
                ps0 += __shfl_xor_sync(0xffffffffu, ps0, o);
                pq0 += __shfl_xor_sync(0xffffffffu, pq0, o);
                ps1 += __shfl_xor_sync(0xffffffffu, ps1, o);
                pq1 += __shfl_xor_sync(0xffffffffu, pq1, o);
            }
            if ((l & 3) == 0)
                *(float4*)&pbuf[(wg * 8 + (l >> 2)) * 4] = make_float4(ps0, pq0, ps1, pq1);
            barg(g);   // partials visible; ALL stage-A Xs reads done

            // prefetch next tile (Xs now free)
            {
                int tn = t + stride;
                if (tn < nTiles) prefetch(tn * 64, p ? sh0 : sh1, p ? dst0 : dst1);
                asm volatile("cp.async.commit_group;" ::: "memory");
            }

            // merge partner warp's partials -> full 64-col row stats
            float4 pp = *(const float4*)&pbuf[((wg ^ 1) * 8 + (l >> 2)) * 4];
            ps0 += pp.x; pq0 += pp.y; ps1 += pp.z; pq1 += pp.w;
            float mu0   = ps0 * (1.f / 64.f);
            float rstd0 = rsqrtf(pq0 * (1.f / 64.f) - mu0 * mu0 + 1e-5f);
            float mu1   = ps1 * (1.f / 64.f);
            float rstd1 = rsqrtf(pq1 * (1.f / 64.f) - mu1 * mu1 + 1e-5f);

            // normalize + silu + tf32, store G
            const int r0 = m0 + (l >> 2);
            #pragma unroll
            for (int nt = 0; nt < 4; nt++) {
                int c = nq * 32 + nt * 8 + (l & 3) * 2;
                float g0 = gms[c], g1 = gms[c + 1];
                float q0 = bts[c], q1 = bts[c + 1];
                float v00 = (d[nt][0] - mu0) * rstd0 * g0 + q0;
                float v01 = (d[nt][1] - mu0) * rstd0 * g1 + q1;
                float v10 = (d[nt][2] - mu1) * rstd1 * g0 + q0;
                float v11 = (d[nt][3] - mu1) * rstd1 * g1 + q1;
                v00 = __fdividef(v00, 1.f + __expf(-v00));
                v01 = __fdividef(v01, 1.f + __expf(-v01));
                v10 = __fdividef(v10, 1.f + __expf(-v10));
                v11 = __fdividef(v11, 1.f + __expf(-v11));
                *(uint2*)&Gs[r0 * GSTR + c]       = make_uint2(f2tf32(v00), f2tf32(v01));
                *(uint2*)&Gs[(r0 + 8) * GSTR + c] = make_uint2(f2tf32(v10), f2tf32(v11));
            }
        }
        barg(g);   // G visible to group

        // -------- stage B: t[64x224] = G @ M + c (mma tf32) --------
        float d[2][7][4] = {};
        const int mg = wg & 1;
        const int ng = wg >> 1;          // 0..3
        {
            const int m0 = mg * 32;
            const int n0 = ng * 56;
            const uint32_t* Gu = (const uint32_t*)Gs;
            const float2* M2 = (const float2*)Ms;
            const int ar00 = (m0 + (l >> 2)) * GSTR + (l & 3);
            const int bcol = n0 + (l >> 2);

            #pragma unroll
            for (int k0 = 0; k0 < 64; k0 += 8) {
                uint32_t a[2][4];
                #pragma unroll
                for (int mt = 0; mt < 2; mt++) {
                    int base = ar00 + mt * 16 * GSTR + k0;
                    a[mt][0] = Gu[base];
                    a[mt][1] = Gu[base + 8 * GSTR];
                    a[mt][2] = Gu[base + 4];
                    a[mt][3] = Gu[base + 8 * GSTR + 4];
                }
                const int brow = ((k0 >> 3) * 4 + (l & 3)) * MSTR2 + bcol;
                #pragma unroll
                for (int jt = 0; jt < 7; jt++) {
                    float2 bb = M2[brow + jt * 8];
                    uint32_t b0 = __float_as_uint(bb.x);
                    uint32_t b1 = __float_as_uint(bb.y);
                    mma_tf32(d[0][jt], a[0], b0, b1);
                    mma_tf32(d[1][jt], a[1], b0, b1);
                }
            }
        }

        // -------- stage C: two halves of 32 edges --------
        #pragma unroll
        for (int half = 0; half < 2; half++) {
            barg(g);   // prev tS reads done / stage-B Gs reads done
            if (mg == half) {
                const int n0 = ng * 56;
                #pragma unroll
                for (int jt = 0; jt < 7; jt++) {
                    int c = n0 + jt * 8 + (l & 3) * 2;
                    float c0 = cS[c], c1 = cS[c + 1];
                    #pragma unroll
                    for (int mt = 0; mt < 2; mt++) {
                        int r0 = mt * 16 + (l >> 2);
                        *(float2*)&tS[r0 * TSTR + c] =
                            make_float2(d[mt][jt][0] + c0, d[mt][jt][1] + c1);
                        *(float2*)&tS[(r0 + 8) * TSTR + c] =
                            make_float2(d[mt][jt][2] + c0, d[mt][jt][3] + c1);
                    }
                }
            }
            barg(g);

            // balanced coalesced scatter: 8 warps x 4 edges
            const float4 b0v = *(const float4*)&b0s[l * 4];
            #pragma unroll 1
            for (int i = 0; i < 4; i++) {
                const int er = wg * 4 + i;            // row in tS (0..31)
                const int e  = half * 32 + er;        // edge in tile
                if (e0 + e >= E) continue;
                const float* te = &tS[er * TSTR];
                const float* sh = &shP[e * 9];
                float* base = out + (size_t)dstP[e] * 480;
                const float s0 = sh[0];

                {
                    float4 v = *(const float4*)&te[l * 4];
                    red4(base + l * 4,
                         fmaf(s0, v.x, b0v.x), fmaf(s0, v.y, b0v.y),
                         fmaf(s0, v.z, b0v.z), fmaf(s0, v.w, b0v.w));
                }
                #pragma unroll
                for (int r = 0; r < 2; r++) {
                    int j = l + r * 32;
                    if (j < 48) {
                        int pidx = 4 * j;
                        int q = (pidx * 0x5556) >> 16;
                        int m = pidx - 3 * q;
                        float ta = te[128 + q];
                        float tb = te[128 + q + 1];
                        float v[4];
                        #pragma unroll
                        for (int ii = 0; ii < 4; ii++) {
                            int mi = m + ii;
                            int f  = (mi >= 3);
                            float sv = sh[1 + mi - 3 * f];
                            v[ii] = (f ? tb : ta) * sv;
                        }
                        red4(base + 128 + pidx, v[0], v[1], v[2], v[3]);
                    }
                }
                #pragma unroll
                for (int r = 0; r < 2; r++) {
                    int j = l + r * 32;
                    if (j < 40) {
                        int pidx = 4 * j;
                        int q = (pidx * 0x3334) >> 16;
                        int m = pidx - 5 * q;
                        int qb = (q + 1 > 31) ? 31 : q + 1;
                        float ta = te[192 + q];
                        float tb = te[192 + qb];
                        float v[4];
                        #pragma unroll
                        for (int ii = 0; ii < 4; ii++) {
                            int mi = m + ii;
                            int f  = (mi >= 5);
                            float sv = sh[4 + mi - 5 * f];
                            v[ii] = (f ? tb : ta) * sv;
                        }
                        red4(base + 320 + pidx, v[0], v[1], v[2], v[3]);
                    }
                }
            }
        }
        p ^= 1;
    }
}

// ---------------------------------------------------------------------------
extern "C" void kernel_launch(void* const* d_in, const int* in_sizes, int n_in,
                              void* d_out, int out_size) {
    const float* edge_attr    = (const float*)d_in[1];
    const float* edge_scalars = (const float*)d_in[2];
    const int*   edge_dst     = (const int*)d_in[4];
    const float* exp_w   = (const float*)d_in[6];
    const float* exp_b   = (const float*)d_in[7];
    const float* rad_w1  = (const float*)d_in[8];
    const float* rad_b1  = (const float*)d_in[9];
    const float* rad_gamma = (const float*)d_in[10];
    const float* rad_beta  = (const float*)d_in[11];
    const float* rad_w2  = (const float*)d_in[12];
    const float* rad_b2  = (const float*)d_in[13];
    const float* proj_w0 = (const float*)d_in[14];
    const float* proj_b0 = (const float*)d_in[15];
    const float* proj_w1 = (const float*)d_in[16];
    const float* proj_w2 = (const float*)d_in[17];
    float* out = (float*)d_out;
    const int E = in_sizes[4];

    cudaMemsetAsync(d_out, 0, (size_t)out_size * sizeof(float));

    precompute_kernel<<<69, 1024>>>(exp_w, exp_b, rad_w2, rad_b2,
                                    proj_w0, proj_w1, proj_w2, rad_w1);

    const size_t SMEM_FLOATS = CONST_OFF + 64 * 3 + 256 + 128;   // 54592
    const size_t SMEM_BYTES = SMEM_FLOATS * sizeof(float);        // 218368
    cudaFuncSetAttribute(edge_main_kernel,
                         cudaFuncAttributeMaxDynamicSharedMemorySize, (int)SMEM_BYTES);

    int sms = 148;
    cudaDeviceGetAttribute(&sms, cudaDevAttrMultiProcessorCount, 0);
    const int nTiles = (E + 63) / 64;
    int grid = (nTiles + 1) / 2;
    if (grid > sms) grid = sms;

    edge_main_kernel<<<grid, THREADS, SMEM_BYTES>>>(
        edge_attr, edge_scalars, edge_dst,
        rad_b1, rad_gamma, rad_beta,
        proj_b0, out, E, nTiles);
}

// round 11
// speedup vs baseline: 1.3421x; 1.0106x over previous
#include <cuda_runtime.h>
#include <cuda_bf16.h>
#include <cstdint>

#define THREADS 512
#define RCOLS   224
#define MSTR2   228     // Ms row stride in float2 (mod 16 == 4 -> conflict-free LDS.64)
#define XSTR    68      // Xs row stride (mod 32 == 4 -> conflict-free A frags)
#define GSTR    68
#define W1STR2  68      // W1 row stride in float2 (mod 16 == 4)
#define TSTR    228     // t staging row stride (32 rows per half)

// group-local smem block sizes (floats)
#define GRP_FLOATS (4352 + 4352 + 7296 + 2*576 + 2*64 + 256)   // 17536
#define MS_FLOATS  (32 * MSTR2 * 2)                             // 14592
#define W1_FLOATS  (32 * W1STR2 * 2)                            // 4352
#define CONST_OFF  (MS_FLOATS + W1_FLOATS + 2 * GRP_FLOATS)     // 54016

// Precomputed fused weight M, row-pair packed:
//   g_M[(prow*224 + col)*2 + slot],  prow=(k>>3)*4+(k&3), slot=(k>>2)&1
// bias row c[256] (fp32), W1 packed the same way (64 cols).
__device__ __align__(16) float g_M[32 * 224 * 2];
__device__ __align__(16) float g_c[256];
__device__ __align__(16) float g_W1[32 * 64 * 2];

__device__ __forceinline__ uint32_t f2tf32(float f) {
    uint32_t u;
    asm("cvt.rna.tf32.f32 %0, %1;" : "=r"(u) : "f"(f));
    return u;
}

// ---------------------------------------------------------------------------
// Precompute: c-loop split 4-way across threads, smem reduce.
// Blocks 0..64: M rows (64 = bias row). Blocks 65..68: W1 tf32 conversion.
// Both weights written in row-pair-packed float2 layout.
// ---------------------------------------------------------------------------
__global__ __launch_bounds__(1024)
void precompute_kernel(const float* __restrict__ exp_w,
                       const float* __restrict__ exp_b,
                       const float* __restrict__ rad_w2,
                       const float* __restrict__ rad_b2,
                       const float* __restrict__ pw0,
                       const float* __restrict__ pw1,
                       const float* __restrict__ pw2,
                       const float* __restrict__ rad_w1) {
    int k = blockIdx.x;
    int tid = threadIdx.x;

    if (k >= 65) {                       // W1 conversion: 4 blocks x 1024
        int i = (k - 65) * 1024 + tid;
        if (i < 64 * 64) {
            int kk = i >> 6, col = i & 63;
            int prow = (kk >> 3) * 4 + (kk & 3);
            int slot = (kk >> 2) & 1;
            g_W1[prow * 128 + col * 2 + slot] = __uint_as_float(f2tf32(rad_w1[i]));
        }
        return;
    }

    __shared__ float s_s[128];
    __shared__ float s_w[384];
    __shared__ float part[4][256];

    if (tid < 128) s_s[tid] = exp_w[tid] + exp_b[tid];
    if (tid >= 128 && tid < 512) {
        int i = tid - 128;
        s_w[i] = (k < 64) ? rad_w2[k * 384 + i] : rad_b2[i];
    }
    __syncthreads();

    const int cs  = tid >> 8;    // 0..3: c chunk
    const int col = tid & 255;   // 0..255
    float acc = 0.f;
    if (col < RCOLS) {
        const float* P;
        int d, woff, pstride;
        if (col < 128)      { P = pw0; d = col;       woff = 0;   pstride = 128; }
        else if (col < 192) { P = pw1; d = col - 128; woff = 128; pstride = 64;  }
        else                { P = pw2; d = col - 192; woff = 256; pstride = 32;  }
        const int c0 = cs * 32;
        #pragma unroll 8
        for (int c = c0; c < c0 + 32; c++)
            acc += s_w[woff + c] * s_s[c] * __ldg(&P[c * pstride + d]);
    }
    part[cs][col] = acc;
    __syncthreads();

    if (tid < 256) {
        float sum = (part[0][tid] + part[1][tid]) + (part[2][tid] + part[3][tid]);
        sum *= 0.25f;   // 1/sqrt(AVG_AGG)
        if (k < 64) {
            if (tid < RCOLS) {
                int prow = (k >> 3) * 4 + (k & 3);
                int slot = (k >> 2) & 1;
                g_M[(prow * 224 + tid) * 2 + slot] = __uint_as_float(f2tf32(sum));
            }
        } else {
            g_c[tid] = sum;
        }
    }
}

// ---------------------------------------------------------------------------
__device__ __forceinline__ void red4(float* p, float a, float b, float c, float d) {
    asm volatile("red.global.add.v4.f32 [%0], {%1, %2, %3, %4};"
                 :: "l"(p), "f"(a), "f"(b), "f"(c), "f"(d) : "memory");
}

__device__ __forceinline__ void cp_async16(void* smem_ptr, const void* gmem) {
    uint32_t s = (uint32_t)__cvta_generic_to_shared(smem_ptr);
    asm volatile("cp.async.cg.shared.global [%0], [%1], 16;" :: "r"(s), "l"(gmem));
}
__device__ __forceinline__ void cp_async16_zfill(void* smem_ptr, const void* gmem, int srcsz) {
    uint32_t s = (uint32_t)__cvta_generic_to_shared(smem_ptr);
    asm volatile("cp.async.cg.shared.global [%0], [%1], 16, %2;"
                 :: "r"(s), "l"(gmem), "r"(srcsz));
}

__device__ __forceinline__ void mma_tf32(float d[4], const uint32_t a[4],
                                         uint32_t b0, uint32_t b1) {
    asm volatile(
        "mma.sync.aligned.m16n8k8.row.col.f32.tf32.tf32.f32 "
        "{%0,%1,%2,%3}, {%4,%5,%6,%7}, {%8,%9}, {%0,%1,%2,%3};"
        : "+f"(d[0]), "+f"(d[1]), "+f"(d[2]), "+f"(d[3])
        : "r"(a[0]), "r"(a[1]), "r"(a[2]), "r"(a[3]), "r"(b0), "r"(b1));
}

// group barrier (named): 256 threads of group g
__device__ __forceinline__ void barg(int g) {
    asm volatile("bar.sync %0, %1;" :: "r"(g + 1), "r"(256) : "memory");
}

// ---------------------------------------------------------------------------
// Persistent kernel, two independent 256-thread warp-groups per CTA.
// Each group owns a stream of 64-edge tiles; groups overlap GEMM vs scatter.
// Scatter uses merged branchless region-1/2 rounds (4 red4 per edge).
// ---------------------------------------------------------------------------
__global__ __launch_bounds__(THREADS, 1)
void edge_main_kernel(const float* __restrict__ edge_attr,
                      const float* __restrict__ edge_scalars,
                      const int*   __restrict__ edge_dst,
                      const float* __restrict__ rad_b1,
                      const float* __restrict__ rad_gamma,
                      const float* __restrict__ rad_beta,
                      const float* __restrict__ proj_b0,
                      float* __restrict__ out,
                      int E, int nTiles)
{
    extern __shared__ float smem[];
    float* Ms   = smem;                     // 14592 (32 x 228 float2)
    float* W1s  = Ms + MS_FLOATS;           // 4352  (32 x 68 float2)
    // constants
    float* b1s  = smem + CONST_OFF;         // 64
    float* gms  = b1s + 64;                 // 64
    float* bts  = gms + 64;                 // 64
    float* cS   = bts + 64;                 // 256
    float* b0s  = cS + 256;                 // 128

    const int tid = threadIdx.x;
    const int g   = tid >> 8;        // warp-group 0/1
    const int gt  = tid & 255;       // thread-in-group
    const int l   = tid & 31;
    const int wg  = (tid >> 5) & 7;  // warp-in-group 0..7

    // group-local buffers
    float* GB   = smem + MS_FLOATS + W1_FLOATS + g * GRP_FLOATS;
    float* Xs   = GB;                       // 64*68 = 4352
    float* Gs   = Xs + 4352;                // 64*68 = 4352
    float* tS   = Gs + 4352;                // 32*228 = 7296
    float* sh0  = tS + 7296;                // 576
    float* sh1  = sh0 + 576;                // 576
    int*   dst0 = (int*)(sh1 + 576);        // 64
    int*   dst1 = dst0 + 64;                // 64
    float* pbuf = (float*)(dst1 + 64);      // 256

    // -------- one-time loads (all 512 threads): M, W1, constants --------
    for (int i = tid; i < 32 * 112; i += THREADS) {
        int row = i / 112, c4 = i - row * 112;
        cp_async16(&Ms[row * (MSTR2 * 2) + c4 * 4], &g_M[row * 448 + c4 * 4]);
    }
    for (int i = tid; i < 32 * 32; i += THREADS) {
        int row = i >> 5, c4 = i & 31;
        cp_async16(&W1s[row * (W1STR2 * 2) + c4 * 4], &g_W1[row * 128 + c4 * 4]);
    }
    if (tid < 64) { b1s[tid] = rad_b1[tid]; gms[tid] = rad_gamma[tid]; bts[tid] = rad_beta[tid]; }
    if (tid >= 64 && tid < 64 + 256) cS[tid - 64] = g_c[tid - 64];
    if (tid >= 320 && tid < 448) b0s[tid - 320] = proj_b0[tid - 320] * 0.25f;

    // -------- per-group tile prefetch (64 edges) --------
    auto prefetch = [&](int e0, float* shB, int* dstB) {
        if (e0 + 64 <= E) {   // full tile: no bounds math
            const float* xg = edge_scalars + (size_t)e0 * 64;
            #pragma unroll
            for (int r = 0; r < 4; r++) {
                int i = gt + r * 256;            // 0..1023
                int e = i >> 4, c4 = i & 15;
                cp_async16(&Xs[e * XSTR + c4 * 4], xg + e * 64 + c4 * 4);
            }
            if (gt < 144)
                cp_async16(&shB[gt * 4], edge_attr + (size_t)e0 * 9 + gt * 4);
            if (gt < 16)
                cp_async16(&dstB[gt * 4], edge_dst + e0 + gt * 4);
        } else {
            #pragma unroll
            for (int r = 0; r < 4; r++) {
                int i = gt + r * 256;
                int e = i >> 4, c4 = i & 15;
                int ge = e0 + e;
                int gc = (ge < E) ? ge : (E - 1);
                cp_async16_zfill(&Xs[e * XSTR + c4 * 4],
                                 edge_scalars + (size_t)gc * 64 + c4 * 4,
                                 (ge < E) ? 16 : 0);
            }
            if (gt < 144) {
                long rem = (long)E * 9 - (long)e0 * 9 - (long)gt * 4;
                int sz = (rem >= 4) ? 16 : ((rem > 0) ? (int)(rem * 4) : 0);
                cp_async16_zfill(&shB[gt * 4], edge_attr + (size_t)e0 * 9 + gt * 4, sz);
            }
            if (gt < 16) {
                int off = gt * 4;
                int ge = e0 + off;
                int gc = (ge + 3 < E) ? ge : ((E >= 4) ? E - 4 : 0);
                int rem = E - ge;
                int sz = (rem >= 4) ? 16 : ((rem > 0) ? rem * 4 : 0);
                cp_async16_zfill(&dstB[off], edge_dst + gc, sz);
            }
        }
    };

    const int stride = gridDim.x * 2;
    int t0 = blockIdx.x * 2 + g;
    if (t0 < nTiles) prefetch(t0 * 64, sh0, dst0);
    asm volatile("cp.async.commit_group;" ::: "memory");
    __syncthreads();   // constants visible; groups diverge after this

    int p = 0;
    for (int t = t0; t < nTiles; t += stride) {
        const int e0 = t * 64;
        float* shP  = p ? sh1 : sh0;
        int*   dstP = p ? dst1 : dst0;

        asm volatile("cp.async.wait_group 0;" ::: "memory");
        barg(g);

        // -------- stage A: h[64x64] = X @ W1 (mma tf32), LN fused --------
        {
            const int mt = wg >> 1;          // 0..3
            const int nq = wg & 1;
            const int m0 = mt * 16;
            float d[4][4] = {};
            const int ar0 = (m0 + (l >> 2)) * XSTR + (l & 3);
            const int ar1 = ar0 + 8 * XSTR;
            const float2* W2 = (const float2*)W1s;
            const int wcol = nq * 32 + (l >> 2);   // float2 col base

            #pragma unroll
            for (int k0 = 0; k0 < 64; k0 += 8) {
                uint32_t a[4];
                a[0] = f2tf32(Xs[ar0 + k0]);
                a[1] = f2tf32(Xs[ar1 + k0]);
                a[2] = f2tf32(Xs[ar0 + k0 + 4]);
                a[3] = f2tf32(Xs[ar1 + k0 + 4]);
                const int wrow = ((k0 >> 3) * 4 + (l & 3)) * W1STR2 + wcol;
                #pragma unroll
                for (int nt = 0; nt < 4; nt++) {
                    float2 bb = W2[wrow + nt * 8];
                    mma_tf32(d[nt], a, __float_as_uint(bb.x), __float_as_uint(bb.y));
                }
            }

            // bias + per-row partial sums over this warp's 32 cols
            float ps0 = 0.f, pq0 = 0.f, ps1 = 0.f, pq1 = 0.f;
            #pragma unroll
            for (int nt = 0; nt < 4; nt++) {
                int c = nq * 32 + nt * 8 + (l & 3) * 2;
                float b0 = b1s[c], b1 = b1s[c + 1];
                d[nt][0] += b0; d[nt][1] += b1;
                d[nt][2] += b0; d[nt][3] += b1;
                ps0 += d[nt][0] + d[nt][1];
                pq0 += d[nt][0] * d[nt][0] + d[nt][1] * d[nt][1];
                ps1 += d[nt][2] + d[nt][3];
                pq1 += d[nt][2] * d[nt][2] + d[nt][3] * d[nt][3];
            }
            #pragma unroll
            for (int o = 1; o <= 2; o <<= 1) {
                ps0 += __shfl_xor_sync(0xffffffffu, ps0, o);
                pq0 += __shfl_xor_sync(0xffffffffu, pq0, o);
                ps1 += __shfl_xor_sync(0xffffffffu, ps1, o);
                pq1 += __shfl_xor_sync(0xffffffffu, pq1, o);
            }
            if ((l & 3) == 0)
                *(float4*)&pbuf[(wg * 8 + (l >> 2)) * 4] = make_float4(ps0, pq0, ps1, pq1);
            barg(g);   // partials visible; ALL stage-A Xs reads done

            // prefetch next tile (Xs now free)
            {
                int tn = t + stride;
                if (tn < nTiles) prefetch(tn * 64, p ? sh0 : sh1, p ? dst0 : dst1);
                asm volatile("cp.async.commit_group;" ::: "memory");
            }

            // merge partner warp's partials -> full 64-col row stats
            float4 pp = *(const float4*)&pbuf[((wg ^ 1) * 8 + (l >> 2)) * 4];
            ps0 += pp.x; pq0 += pp.y; ps1 += pp.z; pq1 += pp.w;
            float mu0   = ps0 * (1.f / 64.f);
            float rstd0 = rsqrtf(pq0 * (1.f / 64.f) - mu0 * mu0 + 1e-5f);
            float mu1   = ps1 * (1.f / 64.f);
            float rstd1 = rsqrtf(pq1 * (1.f / 64.f) - mu1 * mu1 + 1e-5f);

            // normalize + silu + tf32, store G
            const int r0 = m0 + (l >> 2);
            #pragma unroll
            for (int nt = 0; nt < 4; nt++) {
                int c = nq * 32 + nt * 8 + (l & 3) * 2;
                float g0 = gms[c], g1 = gms[c + 1];
                float q0 = bts[c], q1 = bts[c + 1];
                float v00 = (d[nt][0] - mu0) * rstd0 * g0 + q0;
                float v01 = (d[nt][1] - mu0) * rstd0 * g1 + q1;
                float v10 = (d[nt][2] - mu1) * rstd1 * g0 + q0;
                float v11 = (d[nt][3] - mu1) * rstd1 * g1 + q1;
                v00 = __fdividef(v00, 1.f + __expf(-v00));
                v01 = __fdividef(v01, 1.f + __expf(-v01));
                v10 = __fdividef(v10, 1.f + __expf(-v10));
                v11 = __fdividef(v11, 1.f + __expf(-v11));
                *(uint2*)&Gs[r0 * GSTR + c]       = make_uint2(f2tf32(v00), f2tf32(v01));
                *(uint2*)&Gs[(r0 + 8) * GSTR + c] = make_uint2(f2tf32(v10), f2tf32(v11));
            }
        }
        barg(g);   // G visible to group

        // -------- stage B: t[64x224] = G @ M + c (mma tf32) --------
        float d[2][7][4] = {};
        const int mg = wg & 1;
        const int ng = wg >> 1;          // 0..3
        {
            const int m0 = mg * 32;
            const int n0 = ng * 56;
            const uint32_t* Gu = (const uint32_t*)Gs;
            const float2* M2 = (const float2*)Ms;
            const int ar00 = (m0 + (l >> 2)) * GSTR + (l & 3);
            const int bcol = n0 + (l >> 2);

            #pragma unroll
            for (int k0 = 0; k0 < 64; k0 += 8) {
                uint32_t a[2][4];
                #pragma unroll
                for (int mt = 0; mt < 2; mt++) {
                    int base = ar00 + mt * 16 * GSTR + k0;
                    a[mt][0] = Gu[base];
                    a[mt][1] = Gu[base + 8 * GSTR];
                    a[mt][2] = Gu[base + 4];
                    a[mt][3] = Gu[base + 8 * GSTR + 4];
                }
                const int brow = ((k0 >> 3) * 4 + (l & 3)) * MSTR2 + bcol;
                #pragma unroll
                for (int jt = 0; jt < 7; jt++) {
                    float2 bb = M2[brow + jt * 8];
                    uint32_t b0 = __float_as_uint(bb.x);
                    uint32_t b1 = __float_as_uint(bb.y);
                    mma_tf32(d[0][jt], a[0], b0, b1);
                    mma_tf32(d[1][jt], a[1], b0, b1);
                }
            }
        }

        // -------- stage C: two halves of 32 edges --------
        #pragma unroll
        for (int half = 0; half < 2; half++) {
            barg(g);   // prev tS reads done / stage-B Gs reads done
            if (mg == half) {
                const int n0 = ng * 56;
                #pragma unroll
                for (int jt = 0; jt < 7; jt++) {
                    int c = n0 + jt * 8 + (l & 3) * 2;
                    float c0 = cS[c], c1 = cS[c + 1];
                    #pragma unroll
                    for (int mt = 0; mt < 2; mt++) {
                        int r0 = mt * 16 + (l >> 2);
                        *(float2*)&tS[r0 * TSTR + c] =
                            make_float2(d[mt][jt][0] + c0, d[mt][jt][1] + c1);
                        *(float2*)&tS[(r0 + 8) * TSTR + c] =
                            make_float2(d[mt][jt][2] + c0, d[mt][jt][3] + c1);
                    }
                }
            }
            barg(g);

            // balanced coalesced scatter: 8 warps x 4 edges
            // merged region-1/2 rounds: 4 red4 per edge (1 + 3)
            const float4 b0v = *(const float4*)&b0s[l * 4];
            #pragma unroll 1
            for (int i = 0; i < 4; i++) {
                const int er = wg * 4 + i;            // row in tS (0..31)
                const int e  = half * 32 + er;        // edge in tile
                if (e0 + e >= E) continue;
                const float* te = &tS[er * TSTR];
                const float* sh = &shP[e * 9];
                float* base = out + (size_t)dstP[e] * 480;
                const float s0 = sh[0];

                // region 0: cols 0..127, one red4 per lane
                {
                    float4 v = *(const float4*)&te[l * 4];
                    red4(base + l * 4,
                         fmaf(s0, v.x, b0v.x), fmaf(s0, v.y, b0v.y),
                         fmaf(s0, v.z, b0v.z), fmaf(s0, v.w, b0v.w));
                }
                // regions 1+2 merged: 88 quad-items in 3 rounds
                //   item j<48:  region1, y[128+4j]   = t1[p/3]*sh1[p%3], p=4j
                //   item j>=48: region2, y[320+4jj]  = t2[p/5]*sh2[p%5], p=4jj
                #pragma unroll
                for (int r = 0; r < 3; r++) {
                    int j = l + r * 32;
                    if (j < 88) {
                        int  r2   = (j >= 48);
                        int  jj   = r2 ? (j - 48) : j;
                        int  pidx = 4 * jj;
                        int  q    = r2 ? ((pidx * 0x3334) >> 16)
                                       : ((pidx * 0x5556) >> 16);
                        int  mod  = r2 ? 5 : 3;
                        int  m    = pidx - mod * q;
                        const float* tb_ = te + (r2 ? 192 : 128);
                        int  qb   = q + 1;
                        if (r2 && qb > 31) qb = 31;
                        float ta  = tb_[q];
                        float tbv = tb_[qb];
                        const float* shb = sh + (r2 ? 4 : 1);
                        float v[4];
                        #pragma unroll
                        for (int ii = 0; ii < 4; ii++) {
                            int mi = m + ii;
                            int f  = (mi >= mod);
                            float sv = shb[mi - mod * f];
                            v[ii] = (f ? tbv : ta) * sv;
                        }
                        red4(base + (r2 ? 320 : 128) + pidx, v[0], v[1], v[2], v[3]);
                    }
                }
            }
        }
        p ^= 1;
    }
}

// ---------------------------------------------------------------------------
extern "C" void kernel_launch(void* const* d_in, const int* in_sizes, int n_in,
                              void* d_out, int out_size) {
    const float* edge_attr    = (const float*)d_in[1];
    const float* edge_scalars = (const float*)d_in[2];
    const int*   edge_dst     = (const int*)d_in[4];
    const float* exp_w   = (const float*)d_in[6];
    const float* exp_b   = (const float*)d_in[7];
    const float* rad_w1  = (const float*)d_in[8];
    const float* rad_b1  = (const float*)d_in[9];
    const float* rad_gamma = (const float*)d_in[10];
    const float* rad_beta  = (const float*)d_in[11];
    const float* rad_w2  = (const float*)d_in[12];
    const float* rad_b2  = (const float*)d_in[13];
    const float* proj_w0 = (const float*)d_in[14];
    const float* proj_b0 = (const float*)d_in[15];
    const float* proj_w1 = (const float*)d_in[16];
    const float* proj_w2 = (const float*)d_in[17];
    float* out = (float*)d_out;
    const int E = in_sizes[4];

    cudaMemsetAsync(d_out, 0, (size_t)out_size * sizeof(float));

    precompute_kernel<<<69, 1024>>>(exp_w, exp_b, rad_w2, rad_b2,
                                    proj_w0, proj_w1, proj_w2, rad_w1);

    const size_t SMEM_FLOATS = CONST_OFF + 64 * 3 + 256 + 128;   // 54592
    const size_t SMEM_BYTES = SMEM_FLOATS * sizeof(float);        // 218368
    cudaFuncSetAttribute(edge_main_kernel,
                         cudaFuncAttributeMaxDynamicSharedMemorySize, (int)SMEM_BYTES);

    int sms = 148;
    cudaDeviceGetAttribute(&sms, cudaDevAttrMultiProcessorCount, 0);
    const int nTiles = (E + 63) / 64;
    int grid = (nTiles + 1) / 2;
    if (grid > sms) grid = sms;

    edge_main_kernel<<<grid, THREADS, SMEM_BYTES>>>(
        edge_attr, edge_scalars, edge_dst,
        rad_b1, rad_gamma, rad_beta,
        proj_b0, out, E, nTiles);
}

// round 12
// speedup vs baseline: 1.5541x; 1.1579x over previous
#include <cuda_runtime.h>
#include <cuda_bf16.h>
#include <cstdint>

#define THREADS 512
#define RCOLS   224
#define MSTR2   228     // Ms row stride in float2 (mod 16 == 4 -> conflict-free LDS.64)
#define XSTR    68      // Xs row stride (mod 32 == 4 -> conflict-free A frags)
#define GSTR    68
#define W1STR2  68      // W1 row stride in float2 (mod 16 == 4)
#define TSTR    228     // t staging row stride (16 rows per half)

// group-local smem block sizes (floats)
#define GRP_FLOATS (2176 + 2176 + 3648 + 2*288 + 2*32 + 128)   // 8768
#define MS_FLOATS  (32 * MSTR2 * 2)                             // 14592
#define W1_FLOATS  (32 * W1STR2 * 2)                            // 4352
#define CONST_OFF  (MS_FLOATS + W1_FLOATS + 4 * GRP_FLOATS)     // 54016

// Precomputed fused weight M, row-pair packed:
//   g_M[(prow*224 + col)*2 + slot],  prow=(k>>3)*4+(k&3), slot=(k>>2)&1
// bias row c[256] (fp32), W1 packed the same way (64 cols).
__device__ __align__(16) float g_M[32 * 224 * 2];
__device__ __align__(16) float g_c[256];
__device__ __align__(16) float g_W1[32 * 64 * 2];

__device__ __forceinline__ uint32_t f2tf32(float f) {
    uint32_t u;
    asm("cvt.rna.tf32.f32 %0, %1;" : "=r"(u) : "f"(f));
    return u;
}

// ---------------------------------------------------------------------------
// Precompute: c-loop split 4-way across threads, smem reduce.
// Blocks 0..64: M rows (64 = bias row). Blocks 65..68: W1 tf32 conversion.
// ---------------------------------------------------------------------------
__global__ __launch_bounds__(1024)
void precompute_kernel(const float* __restrict__ exp_w,
                       const float* __restrict__ exp_b,
                       const float* __restrict__ rad_w2,
                       const float* __restrict__ rad_b2,
                       const float* __restrict__ pw0,
                       const float* __restrict__ pw1,
                       const float* __restrict__ pw2,
                       const float* __restrict__ rad_w1) {
    int k = blockIdx.x;
    int tid = threadIdx.x;

    if (k >= 65) {                       // W1 conversion: 4 blocks x 1024
        int i = (k - 65) * 1024 + tid;
        if (i < 64 * 64) {
            int kk = i >> 6, col = i & 63;
            int prow = (kk >> 3) * 4 + (kk & 3);
            int slot = (kk >> 2) & 1;
            g_W1[prow * 128 + col * 2 + slot] = __uint_as_float(f2tf32(rad_w1[i]));
        }
        return;
    }

    __shared__ float s_s[128];
    __shared__ float s_w[384];
    __shared__ float part[4][256];

    if (tid < 128) s_s[tid] = exp_w[tid] + exp_b[tid];
    if (tid >= 128 && tid < 512) {
        int i = tid - 128;
        s_w[i] = (k < 64) ? rad_w2[k * 384 + i] : rad_b2[i];
    }
    __syncthreads();

    const int cs  = tid >> 8;    // 0..3: c chunk
    const int col = tid & 255;   // 0..255
    float acc = 0.f;
    if (col < RCOLS) {
        const float* P;
        int d, woff, pstride;
        if (col < 128)      { P = pw0; d = col;       woff = 0;   pstride = 128; }
        else if (col < 192) { P = pw1; d = col - 128; woff = 128; pstride = 64;  }
        else                { P = pw2; d = col - 192; woff = 256; pstride = 32;  }
        const int c0 = cs * 32;
        #pragma unroll 8
        for (int c = c0; c < c0 + 32; c++)
            acc += s_w[woff + c] * s_s[c] * __ldg(&P[c * pstride + d]);
    }
    part[cs][col] = acc;
    __syncthreads();

    if (tid < 256) {
        float sum = (part[0][tid] + part[1][tid]) + (part[2][tid] + part[3][tid]);
        sum *= 0.25f;   // 1/sqrt(AVG_AGG)
        if (k < 64) {
            if (tid < RCOLS) {
                int prow = (k >> 3) * 4 + (k & 3);
                int slot = (k >> 2) & 1;
                g_M[(prow * 224 + tid) * 2 + slot] = __uint_as_float(f2tf32(sum));
            }
        } else {
            g_c[tid] = sum;
        }
    }
}

// ---------------------------------------------------------------------------
__device__ __forceinline__ void red4(float* p, float a, float b, float c, float d) {
    asm volatile("red.global.add.v4.f32 [%0], {%1, %2, %3, %4};"
                 :: "l"(p), "f"(a), "f"(b), "f"(c), "f"(d) : "memory");
}

__device__ __forceinline__ void cp_async16(void* smem_ptr, const void* gmem) {
    uint32_t s = (uint32_t)__cvta_generic_to_shared(smem_ptr);
    asm volatile("cp.async.cg.shared.global [%0], [%1], 16;" :: "r"(s), "l"(gmem));
}
__device__ __forceinline__ void cp_async16_zfill(void* smem_ptr, const void* gmem, int srcsz) {
    uint32_t s = (uint32_t)__cvta_generic_to_shared(smem_ptr);
    asm volatile("cp.async.cg.shared.global [%0], [%1], 16, %2;"
                 :: "r"(s), "l"(gmem), "r"(srcsz));
}

__device__ __forceinline__ void mma_tf32(float d[4], const uint32_t a[4],
                                         uint32_t b0, uint32_t b1) {
    asm volatile(
        "mma.sync.aligned.m16n8k8.row.col.f32.tf32.tf32.f32 "
        "{%0,%1,%2,%3}, {%4,%5,%6,%7}, {%8,%9}, {%0,%1,%2,%3};"
        : "+f"(d[0]), "+f"(d[1]), "+f"(d[2]), "+f"(d[3])
        : "r"(a[0]), "r"(a[1]), "r"(a[2]), "r"(a[3]), "r"(b0), "r"(b1));
}

// group barrier (named): 128 threads of group g
__device__ __forceinline__ void barg(int g) {
    asm volatile("bar.sync %0, %1;" :: "r"(g + 1), "r"(128) : "memory");
}

// ---------------------------------------------------------------------------
// Persistent kernel, FOUR independent 128-thread warp-groups per CTA.
// Each group owns a stream of 32-edge tiles; groups overlap GEMM vs scatter.
// ---------------------------------------------------------------------------
__global__ __launch_bounds__(THREADS, 1)
void edge_main_kernel(const float* __restrict__ edge_attr,
                      const float* __restrict__ edge_scalars,
                      const int*   __restrict__ edge_dst,
                      const float* __restrict__ rad_b1,
                      const float* __restrict__ rad_gamma,
                      const float* __restrict__ rad_beta,
                      const float* __restrict__ proj_b0,
                      float* __restrict__ out,
                      int E, int nTiles)
{
    extern __shared__ float smem[];
    float* Ms   = smem;                     // 14592 (32 x 228 float2)
    float* W1s  = Ms + MS_FLOATS;           // 4352  (32 x 68 float2)
    // constants
    float* b1s  = smem + CONST_OFF;         // 64
    float* gms  = b1s + 64;                 // 64
    float* bts  = gms + 64;                 // 64
    float* cS   = bts + 64;                 // 256
    float* b0s  = cS + 256;                 // 128

    const int tid = threadIdx.x;
    const int g   = tid >> 7;        // warp-group 0..3
    const int gt  = tid & 127;       // thread-in-group
    const int l   = tid & 31;
    const int wg  = (tid >> 5) & 3;  // warp-in-group 0..3

    // group-local buffers
    float* GB   = smem + MS_FLOATS + W1_FLOATS + g * GRP_FLOATS;
    float* Xs   = GB;                       // 32*68 = 2176
    float* Gs   = Xs + 2176;                // 32*68 = 2176
    float* tS   = Gs + 2176;                // 16*228 = 3648
    float* sh0  = tS + 3648;                // 288
    float* sh1  = sh0 + 288;                // 288
    int*   dst0 = (int*)(sh1 + 288);        // 32
    int*   dst1 = dst0 + 32;                // 32
    float* pbuf = (float*)(dst1 + 32);      // 128

    // -------- one-time loads (all 512 threads): M, W1, constants --------
    for (int i = tid; i < 32 * 112; i += THREADS) {
        int row = i / 112, c4 = i - row * 112;
        cp_async16(&Ms[row * (MSTR2 * 2) + c4 * 4], &g_M[row * 448 + c4 * 4]);
    }
    for (int i = tid; i < 32 * 32; i += THREADS) {
        int row = i >> 5, c4 = i & 31;
        cp_async16(&W1s[row * (W1STR2 * 2) + c4 * 4], &g_W1[row * 128 + c4 * 4]);
    }
    if (tid < 64) { b1s[tid] = rad_b1[tid]; gms[tid] = rad_gamma[tid]; bts[tid] = rad_beta[tid]; }
    if (tid >= 64 && tid < 64 + 256) cS[tid - 64] = g_c[tid - 64];
    if (tid >= 320 && tid < 448) b0s[tid - 320] = proj_b0[tid - 320] * 0.25f;

    // -------- per-group tile prefetch (32 edges) --------
    auto prefetch = [&](int e0, float* shB, int* dstB) {
        if (e0 + 32 <= E) {   // full tile: no bounds math
            const float* xg = edge_scalars + (size_t)e0 * 64;
            #pragma unroll
            for (int r = 0; r < 4; r++) {
                int i = gt + r * 128;            // 0..511
                int e = i >> 4, c4 = i & 15;
                cp_async16(&Xs[e * XSTR + c4 * 4], xg + e * 64 + c4 * 4);
            }
            if (gt < 72)
                cp_async16(&shB[gt * 4], edge_attr + (size_t)e0 * 9 + gt * 4);
            if (gt < 8)
                cp_async16(&dstB[gt * 4], edge_dst + e0 + gt * 4);
        } else {
            #pragma unroll
            for (int r = 0; r < 4; r++) {
                int i = gt + r * 128;
                int e = i >> 4, c4 = i & 15;
                int ge = e0 + e;
                int gc = (ge < E) ? ge : (E - 1);
                cp_async16_zfill(&Xs[e * XSTR + c4 * 4],
                                 edge_scalars + (size_t)gc * 64 + c4 * 4,
                                 (ge < E) ? 16 : 0);
            }
            if (gt < 72) {
                long rem = (long)E * 9 - (long)e0 * 9 - (long)gt * 4;
                int sz = (rem >= 4) ? 16 : ((rem > 0) ? (int)(rem * 4) : 0);
                cp_async16_zfill(&shB[gt * 4], edge_attr + (size_t)e0 * 9 + gt * 4, sz);
            }
            if (gt < 8) {
                int off = gt * 4;
                int ge = e0 + off;
                int gc = (ge + 3 < E) ? ge : ((E >= 4) ? E - 4 : 0);
                int rem = E - ge;
                int sz = (rem >= 4) ? 16 : ((rem > 0) ? rem * 4 : 0);
                cp_async16_zfill(&dstB[off], edge_dst + gc, sz);
            }
        }
    };

    const int stride = gridDim.x * 4;
    int t0 = blockIdx.x * 4 + g;
    if (t0 < nTiles) prefetch(t0 * 32, sh0, dst0);
    asm volatile("cp.async.commit_group;" ::: "memory");
    __syncthreads();   // constants visible; groups diverge after this

    int p = 0;
    for (int t = t0; t < nTiles; t += stride) {
        const int e0 = t * 32;
        float* shP  = p ? sh1 : sh0;
        int*   dstP = p ? dst1 : dst0;

        asm volatile("cp.async.wait_group 0;" ::: "memory");
        barg(g);

        // -------- stage A: h[32x64] = X @ W1 (mma tf32), LN fused --------
        {
            const int mt = wg >> 1;          // 0..1
            const int nq = wg & 1;
            const int m0 = mt * 16;
            float d[4][4] = {};
            const int ar0 = (m0 + (l >> 2)) * XSTR + (l & 3);
            const int ar1 = ar0 + 8 * XSTR;
            const float2* W2 = (const float2*)W1s;
            const int wcol = nq * 32 + (l >> 2);   // float2 col base

            #pragma unroll
            for (int k0 = 0; k0 < 64; k0 += 8) {
                uint32_t a[4];
                a[0] = f2tf32(Xs[ar0 + k0]);
                a[1] = f2tf32(Xs[ar1 + k0]);
                a[2] = f2tf32(Xs[ar0 + k0 + 4]);
                a[3] = f2tf32(Xs[ar1 + k0 + 4]);
                const int wrow = ((k0 >> 3) * 4 + (l & 3)) * W1STR2 + wcol;
                #pragma unroll
                for (int nt = 0; nt < 4; nt++) {
                    float2 bb = W2[wrow + nt * 8];
                    mma_tf32(d[nt], a, __float_as_uint(bb.x), __float_as_uint(bb.y));
                }
            }

            // bias + per-row partial sums over this warp's 32 cols
            float ps0 = 0.f, pq0 = 0.f, ps1 = 0.f, pq1 = 0.f;
            #pragma unroll
            for (int nt = 0; nt < 4; nt++) {
                int c = nq * 32 + nt * 8 + (l & 3) * 2;
                float b0 = b1s[c], b1 = b1s[c + 1];
                d[nt][0] += b0; d[nt][1] += b1;
                d[nt][2] += b0; d[nt][3] += b1;
                ps0 += d[nt][0] + d[nt][1];
                pq0 += d[nt][0] * d[nt][0] + d[nt][1] * d[nt][1];
                ps1 += d[nt][2] + d[nt][3];
                pq1 += d[nt][2] * d[nt][2] + d[nt][3] * d[nt][3];
            }
            #pragma unroll
            for (int o = 1; o <= 2; o <<= 1) {
                ps0 += __shfl_xor_sync(0xffffffffu, ps0, o);
                pq0 += __shfl_xor_sync(0xffffffffu, pq0, o);
                ps1 += __shfl_xor_sync(0xffffffffu, ps1, o);
                pq1 += __shfl_xor_sync(0xffffffffu, pq1, o);
            }
            if ((l & 3) == 0)
                *(float4*)&pbuf[(wg * 8 + (l >> 2)) * 4] = make_float4(ps0, pq0, ps1, pq1);
            barg(g);   // partials visible; ALL stage-A Xs reads done

            // prefetch next tile (Xs now free)
            {
                int tn = t + stride;
                if (tn < nTiles) prefetch(tn * 32, p ? sh0 : sh1, p ? dst0 : dst1);
                asm volatile("cp.async.commit_group;" ::: "memory");
            }

            // merge partner warp's partials -> full 64-col row stats
            float4 pp = *(const float4*)&pbuf[((wg ^ 1) * 8 + (l >> 2)) * 4];
            ps0 += pp.x; pq0 += pp.y; ps1 += pp.z; pq1 += pp.w;
            float mu0   = ps0 * (1.f / 64.f);
            float rstd0 = rsqrtf(pq0 * (1.f / 64.f) - mu0 * mu0 + 1e-5f);
            float mu1   = ps1 * (1.f / 64.f);
            float rstd1 = rsqrtf(pq1 * (1.f / 64.f) - mu1 * mu1 + 1e-5f);

            // normalize + silu + tf32, store G
            const int r0 = m0 + (l >> 2);
            #pragma unroll
            for (int nt = 0; nt < 4; nt++) {
                int c = nq * 32 + nt * 8 + (l & 3) * 2;
                float g0 = gms[c], g1 = gms[c + 1];
                float q0 = bts[c], q1 = bts[c + 1];
                float v00 = (d[nt][0] - mu0) * rstd0 * g0 + q0;
                float v01 = (d[nt][1] - mu0) * rstd0 * g1 + q1;
                float v10 = (d[nt][2] - mu1) * rstd1 * g0 + q0;
                float v11 = (d[nt][3] - mu1) * rstd1 * g1 + q1;
                v00 = __fdividef(v00, 1.f + __expf(-v00));
                v01 = __fdividef(v01, 1.f + __expf(-v01));
                v10 = __fdividef(v10, 1.f + __expf(-v10));
                v11 = __fdividef(v11, 1.f + __expf(-v11));
                *(uint2*)&Gs[r0 * GSTR + c]       = make_uint2(f2tf32(v00), f2tf32(v01));
                *(uint2*)&Gs[(r0 + 8) * GSTR + c] = make_uint2(f2tf32(v10), f2tf32(v11));
            }
        }
        barg(g);   // G visible to group

        // -------- stage B: t[32x224] = G @ M + c (mma tf32) --------
        // each warp: all 32 rows x 56 cols (n0 = wg*56)
        float d[2][7][4] = {};
        const int n0 = wg * 56;
        {
            const uint32_t* Gu = (const uint32_t*)Gs;
            const float2* M2 = (const float2*)Ms;
            const int ar00 = (l >> 2) * GSTR + (l & 3);
            const int bcol = n0 + (l >> 2);

            #pragma unroll
            for (int k0 = 0; k0 < 64; k0 += 8) {
                uint32_t a[2][4];
                #pragma unroll
                for (int mt = 0; mt < 2; mt++) {
                    int base = ar00 + mt * 16 * GSTR + k0;
                    a[mt][0] = Gu[base];
                    a[mt][1] = Gu[base + 8 * GSTR];
                    a[mt][2] = Gu[base + 4];
                    a[mt][3] = Gu[base + 8 * GSTR + 4];
                }
                const int brow = ((k0 >> 3) * 4 + (l & 3)) * MSTR2 + bcol;
                #pragma unroll
                for (int jt = 0; jt < 7; jt++) {
                    float2 bb = M2[brow + jt * 8];
                    uint32_t b0 = __float_as_uint(bb.x);
                    uint32_t b1 = __float_as_uint(bb.y);
                    mma_tf32(d[0][jt], a[0], b0, b1);
                    mma_tf32(d[1][jt], a[1], b0, b1);
                }
            }
        }

        // -------- stage C: two halves of 16 edges --------
        #pragma unroll
        for (int half = 0; half < 2; half++) {
            barg(g);   // prev tS reads done / stage-B Gs reads done
            {
                // all 4 warps stage their 56-col slice of this half's 16 rows
                #pragma unroll
                for (int jt = 0; jt < 7; jt++) {
                    int c = n0 + jt * 8 + (l & 3) * 2;
                    float c0 = cS[c], c1 = cS[c + 1];
                    int r0 = (l >> 2);
                    *(float2*)&tS[r0 * TSTR + c] =
                        make_float2(d[half][jt][0] + c0, d[half][jt][1] + c1);
                    *(float2*)&tS[(r0 + 8) * TSTR + c] =
                        make_float2(d[half][jt][2] + c0, d[half][jt][3] + c1);
                }
            }
            barg(g);

            // balanced coalesced scatter: 4 warps x 4 edges
            const float4 b0v = *(const float4*)&b0s[l * 4];
            #pragma unroll 1
            for (int i = 0; i < 4; i++) {
                const int er = wg * 4 + i;            // row in tS (0..15)
                const int e  = half * 16 + er;        // edge in tile
                if (e0 + e >= E) continue;
                const float* te = &tS[er * TSTR];
                const float* sh = &shP[e * 9];
                float* base = out + (size_t)dstP[e] * 480;
                const float s0 = sh[0];

                // region 0: cols 0..127, one red4 per lane
                {
                    float4 v = *(const float4*)&te[l * 4];
                    red4(base + l * 4,
                         fmaf(s0, v.x, b0v.x), fmaf(s0, v.y, b0v.y),
                         fmaf(s0, v.z, b0v.z), fmaf(s0, v.w, b0v.w));
                }
                // regions 1+2 merged: 88 quad-items in 3 rounds
                #pragma unroll
                for (int r = 0; r < 3; r++) {
                    int j = l + r * 32;
                    if (j < 88) {
                        int  r2   = (j >= 48);
                        int  jj   = r2 ? (j - 48) : j;
                        int  pidx = 4 * jj;
                        int  q    = r2 ? ((pidx * 0x3334) >> 16)
                                       : ((pidx * 0x5556) >> 16);
                        int  mod  = r2 ? 5 : 3;
                        int  m    = pidx - mod * q;
                        const float* tb_ = te + (r2 ? 192 : 128);
                        int  qb   = q + 1;
                        if (r2 && qb > 31) qb = 31;
                        float ta  = tb_[q];
                        float tbv = tb_[qb];
                        const float* shb = sh + (r2 ? 4 : 1);
                        float v[4];
                        #pragma unroll
                        for (int ii = 0; ii < 4; ii++) {
                            int mi = m + ii;
                            int f  = (mi >= mod);
                            float sv = shb[mi - mod * f];
                            v[ii] = (f ? tbv : ta) * sv;
                        }
                        red4(base + (r2 ? 320 : 128) + pidx, v[0], v[1], v[2], v[3]);
                    }
                }
            }
        }
        p ^= 1;
    }
}

// ---------------------------------------------------------------------------
extern "C" void kernel_launch(void* const* d_in, const int* in_sizes, int n_in,
                              void* d_out, int out_size) {
    const float* edge_attr    = (const float*)d_in[1];
    const float* edge_scalars = (const float*)d_in[2];
    const int*   edge_dst     = (const int*)d_in[4];
    const float* exp_w   = (const float*)d_in[6];
    const float* exp_b   = (const float*)d_in[7];
    const float* rad_w1  = (const float*)d_in[8];
    const float* rad_b1  = (const float*)d_in[9];
    const float* rad_gamma = (const float*)d_in[10];
    const float* rad_beta  = (const float*)d_in[11];
    const float* rad_w2  = (const float*)d_in[12];
    const float* rad_b2  = (const float*)d_in[13];
    const float* proj_w0 = (const float*)d_in[14];
    const float* proj_b0 = (const float*)d_in[15];
    const float* proj_w1 = (const float*)d_in[16];
    const float* proj_w2 = (const float*)d_in[17];
    float* out = (float*)d_out;
    const int E = in_sizes[4];

    cudaMemsetAsync(d_out, 0, (size_t)out_size * sizeof(float));

    precompute_kernel<<<69, 1024>>>(exp_w, exp_b, rad_w2, rad_b2,
                                    proj_w0, proj_w1, proj_w2, rad_w1);

    const size_t SMEM_FLOATS = CONST_OFF + 64 * 3 + 256 + 128;   // 54592
    const size_t SMEM_BYTES = SMEM_FLOATS * sizeof(float);        // 218368
    cudaFuncSetAttribute(edge_main_kernel,
                         cudaFuncAttributeMaxDynamicSharedMemorySize, (int)SMEM_BYTES);

    int sms = 148;
    cudaDeviceGetAttribute(&sms, cudaDevAttrMultiProcessorCount, 0);
    const int nTiles = (E + 31) / 32;
    int grid = (nTiles + 3) / 4;
    if (grid > sms) grid = sms;

    edge_main_kernel<<<grid, THREADS, SMEM_BYTES>>>(
        edge_attr, edge_scalars, edge_dst,
        rad_b1, rad_gamma, rad_beta,
        proj_b0, out, E, nTiles);
}